// round 2
// baseline (speedup 1.0000x reference)
#include <cuda_runtime.h>
#include <math.h>

#define NODE 112
#define L1D 256
#define L2D 128
#define L3D 64
#define BATCH 2048
#define K1P 56
#define K2P 28

// ---------------- global scratch (no allocations allowed) ----------------
__device__ float g_H0[NODE * L1D];        // projected identity features (batch-indep)
__device__ float g_E1[NODE * NODE];       // exp(relu(s_i + t_j + ba1))   (batch-indep)
__device__ float g_Wp2T[L1D * L2D];       // Wp2 transposed [d][o]
__device__ float g_h1[(size_t)BATCH * NODE * L1D];   // GAT1 output (235 MB)
__device__ float g_hp[(size_t)BATCH * K1P * L1D];    // pooled hidden (117 MB)
__device__ float g_adj[(size_t)BATCH * K1P * K1P];   // pooled normalized adj

// ---------------- K1: batch-independent precompute ----------------
__global__ void k_pre(const float* __restrict__ Wp1, const float* __restrict__ bp1,
                      const float* __restrict__ wa1, const float* __restrict__ wb1,
                      const float* __restrict__ ba1, const float* __restrict__ Wp2) {
    __shared__ float s1[NODE], t1[NODE];
    int t = threadIdx.x;
    for (int idx = t; idx < NODE * L1D; idx += blockDim.x) {
        int n = idx / L1D, o = idx - n * L1D;
        g_H0[idx] = Wp1[o * NODE + n] + bp1[o];
    }
    __syncthreads();
    if (t < NODE) {
        float ss = 0.f, tt = 0.f;
        for (int o = 0; o < L1D; o++) {
            float h = g_H0[t * L1D + o];
            ss += h * wa1[o];
            tt += h * wb1[o];
        }
        s1[t] = ss; t1[t] = tt;
    }
    __syncthreads();
    float ba = ba1[0];
    for (int idx = t; idx < NODE * NODE; idx += blockDim.x) {
        int i = idx / NODE, j = idx - i * NODE;
        float e = s1[i] + t1[j] + ba;
        e = e > 0.f ? e : 0.f;
        g_E1[idx] = expf(e);
    }
    for (int idx = t; idx < L1D * L2D; idx += blockDim.x) {
        int d = idx / L2D, o = idx - d * L2D;
        g_Wp2T[idx] = Wp2[o * L1D + d];
    }
}

// ---------------- K2: GAT1 + pool1 (one CTA per batch, 256 threads) --------
// smem layout (floats):
//   Ws   [112*113]  weighted adjacency, padded stride 113 (conflict-free rowsum)
//   H0t  [112*64]   column tile of H0
//   invr [112]
//   scr  [112]      pool scores accumulator
//   skey [128] + sidx[128] bitonic sort buffers
//   adjb [56*57]    pooled adj staging
#define K2_WS     (NODE * 113)
#define K2_H0T    (K2_WS + NODE * 64)
#define K2_INVR   (K2_H0T + NODE)
#define K2_SCR    (K2_INVR + NODE)
#define K2_SKEY   (K2_SCR + 128)
#define K2_SIDX   (K2_SKEY + 128)          // ints
#define K2_ADJB   (K2_SIDX + K1P * 57)
#define K2_FLOATS (K2_ADJB)

__global__ void __launch_bounds__(256, 2)
k_gat1(const float* __restrict__ x, const float* __restrict__ Wpool1,
       const float* __restrict__ bpool1) {
    extern __shared__ float sm[];
    float* Ws   = sm;
    float* H0t  = sm + K2_WS;
    float* invr = sm + K2_H0T;
    float* scr  = sm + K2_INVR;
    float* skey = sm + K2_SCR;
    int*   sidx = (int*)(sm + K2_SKEY);
    float* adjb = sm + K2_SIDX;

    int b = blockIdx.x;
    int t = threadIdx.x;
    const float* xb = x + (size_t)b * NODE * NODE;

    // W = E1 .* x[b]
    for (int idx = t; idx < NODE * NODE; idx += 256) {
        int i = idx / NODE, j = idx - i * NODE;
        Ws[i * 113 + j] = g_E1[idx] * xb[idx];
    }
    if (t < NODE) scr[t] = 0.f;
    __syncthreads();
    if (t < NODE) {
        float s = 0.f;
        #pragma unroll 8
        for (int j = 0; j < NODE; j++) s += Ws[t * 113 + j];
        invr[t] = 1.f / s;
    }
    __syncthreads();

    int tx = t & 15, ty = t >> 4;       // cols tx*4..+3 (of 64), rows ty*7..+6
    float* h1b = g_h1 + (size_t)b * NODE * L1D;
    float wc0, wc1, wc2, wc3;

    for (int ct = 0; ct < 4; ct++) {
        for (int idx = t; idx < NODE * 64; idx += 256) {
            int j = idx >> 6, c = idx & 63;
            H0t[idx] = g_H0[j * L1D + ct * 64 + c];
        }
        __syncthreads();
        {
            const float* wp = Wpool1 + ct * 64 + tx * 4;
            wc0 = wp[0]; wc1 = wp[1]; wc2 = wp[2]; wc3 = wp[3];
        }
        float acc[7][4];
        #pragma unroll
        for (int r = 0; r < 7; r++) { acc[r][0]=0.f; acc[r][1]=0.f; acc[r][2]=0.f; acc[r][3]=0.f; }

        #pragma unroll 2
        for (int j = 0; j < NODE; j++) {
            float4 bv = *(const float4*)&H0t[j * 64 + tx * 4];
            #pragma unroll
            for (int r = 0; r < 7; r++) {
                float a = Ws[(ty * 7 + r) * 113 + j];
                acc[r][0] = fmaf(a, bv.x, acc[r][0]);
                acc[r][1] = fmaf(a, bv.y, acc[r][1]);
                acc[r][2] = fmaf(a, bv.z, acc[r][2]);
                acc[r][3] = fmaf(a, bv.w, acc[r][3]);
            }
        }
        #pragma unroll
        for (int r = 0; r < 7; r++) {
            int i = ty * 7 + r;
            float ir = invr[i];
            float4 h0v = *(const float4*)&H0t[i * 64 + tx * 4];
            float4 v;
            v.x = fmaxf(fmaf(acc[r][0], ir, h0v.x), 0.f);
            v.y = fmaxf(fmaf(acc[r][1], ir, h0v.y), 0.f);
            v.z = fmaxf(fmaf(acc[r][2], ir, h0v.z), 0.f);
            v.w = fmaxf(fmaf(acc[r][3], ir, h0v.w), 0.f);
            *(float4*)&h1b[i * L1D + ct * 64 + tx * 4] = v;
            float sp = v.x * wc0 + v.y * wc1 + v.z * wc2 + v.w * wc3;
            atomicAdd(&scr[i], sp);
        }
        __syncthreads();
    }

    // pool scores -> sigmoid -> bitonic top-56 (pad to 128)
    if (t < 128) {
        if (t < NODE) {
            skey[t] = 1.f / (1.f + expf(-(scr[t] + bpool1[0])));
            sidx[t] = t;
        } else { skey[t] = -1.f; sidx[t] = t; }
    }
    __syncthreads();
    for (int k = 2; k <= 128; k <<= 1) {
        for (int j = k >> 1; j > 0; j >>= 1) {
            if (t < 128) {
                int l = t ^ j;
                if (l > t) {
                    float a = skey[t], c = skey[l];
                    int ia = sidx[t], ib = sidx[l];
                    bool before = (a > c) || (a == c && ia < ib);
                    bool up = ((t & k) == 0);
                    if (up ? !before : before) {
                        skey[t] = c; skey[l] = a;
                        sidx[t] = ib; sidx[l] = ia;
                    }
                }
            }
            __syncthreads();
        }
    }

    // gather pooled hidden (scaled by score)
    float* hpb = g_hp + (size_t)b * K1P * L1D;
    for (int idx = t; idx < K1P * L1D; idx += 256) {
        int m = idx >> 8, c = idx & 255;
        hpb[idx] = h1b[sidx[m] * L1D + c] * skey[m];
    }
    // pooled adjacency, row-normalized
    for (int idx = t; idx < K1P * K1P; idx += 256) {
        int i = idx / K1P, j = idx - i * K1P;
        adjb[i * 57 + j] = xb[sidx[i] * NODE + sidx[j]];
    }
    __syncthreads();
    if (t < K1P) {
        float s = 0.f;
        for (int j = 0; j < K1P; j++) s += adjb[t * 57 + j];
        invr[t] = 1.f / s;
    }
    __syncthreads();
    float* adjo = g_adj + (size_t)b * K1P * K1P;
    for (int idx = t; idx < K1P * K1P; idx += 256) {
        int i = idx / K1P, j = idx - i * K1P;
        adjo[idx] = adjb[i * 57 + j] * invr[i];
    }
}

// ---------------- K3: GAT2 + pool2 + mean + FC head ----------------
#define K3_HS    (K1P * L1D)                  // 14336
#define K3_W2S   (K3_HS + 64 * L2D)           // +8192
#define K3_H2S   (K3_W2S + K1P * 132)         // +7392
#define K3_H2R   (K3_H2S + K1P * 132)         // +7392
#define K3_ATT   (K3_H2R + K1P * 57)          // +3192
#define K3_S2    (K3_ATT + K1P)
#define K3_T2    (K3_S2 + K1P)
#define K3_SC2   (K3_T2 + K1P)
#define K3_INVR  (K3_SC2 + K1P)
#define K3_SKEY  (K3_INVR + 64)
#define K3_SIDX  (K3_SKEY + 64)               // ints
#define K3_MVEC  (K3_SIDX + L2D)
#define K3_Y1    (K3_MVEC + L3D)
#define K3_FLOATS (K3_Y1)

__global__ void __launch_bounds__(256, 1)
k_gat2(const float* __restrict__ bp2, const float* __restrict__ wa2,
       const float* __restrict__ wb2, const float* __restrict__ ba2,
       const float* __restrict__ Wpool2, const float* __restrict__ bpool2,
       const float* __restrict__ Wfc1, const float* __restrict__ bfc1,
       const float* __restrict__ Wfc2, const float* __restrict__ bfc2,
       float* __restrict__ out) {
    extern __shared__ float sm[];
    float* Hs   = sm;
    float* W2s  = sm + K3_HS;
    float* h2s  = sm + K3_W2S;
    float* h2r  = sm + K3_H2S;
    float* atts = sm + K3_H2R;
    float* s2   = sm + K3_ATT;
    float* t2   = sm + K3_S2;
    float* sc2  = sm + K3_T2;
    float* invr = sm + K3_SC2;
    float* skey = sm + K3_INVR;
    int*   sidx = (int*)(sm + K3_SKEY);
    float* mvec = sm + K3_SIDX;
    float* y1   = sm + K3_MVEC;

    int b = blockIdx.x;
    int t = threadIdx.x;

    for (int idx = t; idx < K1P * L1D; idx += 256)
        Hs[idx] = g_hp[(size_t)b * K1P * L1D + idx];
    if (t < K1P) { s2[t] = 0.f; t2[t] = 0.f; sc2[t] = 0.f; }
    __syncthreads();

    int tx = t & 31, ty = t >> 5;   // cols tx*4..+3 (of 128), rows ty*7..+6 (of 56)

    // h2 = Hs @ Wp2^T + bp2  (56x256 @ 256x128)
    float acc[7][4];
    #pragma unroll
    for (int r = 0; r < 7; r++) { acc[r][0]=0.f; acc[r][1]=0.f; acc[r][2]=0.f; acc[r][3]=0.f; }
    for (int dt = 0; dt < 4; dt++) {
        for (int idx = t; idx < 64 * L2D; idx += 256)
            W2s[idx] = g_Wp2T[(dt * 64) * L2D + idx];
        __syncthreads();
        #pragma unroll 2
        for (int d = 0; d < 64; d++) {
            float4 wv = *(const float4*)&W2s[d * L2D + tx * 4];
            #pragma unroll
            for (int r = 0; r < 7; r++) {
                float a = Hs[(ty * 7 + r) * L1D + dt * 64 + d];
                acc[r][0] = fmaf(a, wv.x, acc[r][0]);
                acc[r][1] = fmaf(a, wv.y, acc[r][1]);
                acc[r][2] = fmaf(a, wv.z, acc[r][2]);
                acc[r][3] = fmaf(a, wv.w, acc[r][3]);
            }
        }
        __syncthreads();
    }
    {
        const float* bpp = bp2 + tx * 4;
        float b0 = bpp[0], b1 = bpp[1], b2 = bpp[2], b3 = bpp[3];
        const float* wap = wa2 + tx * 4;
        const float* wbp = wb2 + tx * 4;
        float wa0=wap[0], wa1v=wap[1], wa2v=wap[2], wa3=wap[3];
        float wb0=wbp[0], wb1v=wbp[1], wb2v=wbp[2], wb3=wbp[3];
        #pragma unroll
        for (int r = 0; r < 7; r++) {
            int i = ty * 7 + r;
            float v0 = acc[r][0] + b0, v1 = acc[r][1] + b1;
            float v2 = acc[r][2] + b2, v3 = acc[r][3] + b3;
            h2s[i * 132 + tx * 4 + 0] = v0;
            h2s[i * 132 + tx * 4 + 1] = v1;
            h2s[i * 132 + tx * 4 + 2] = v2;
            h2s[i * 132 + tx * 4 + 3] = v3;
            atomicAdd(&s2[i], v0 * wa0 + v1 * wa1v + v2 * wa2v + v3 * wa3);
            atomicAdd(&t2[i], v0 * wb0 + v1 * wb1v + v2 * wb2v + v3 * wb3);
        }
    }
    __syncthreads();

    // attention weights
    float ba = ba2[0];
    const float* adjb = g_adj + (size_t)b * K1P * K1P;
    for (int idx = t; idx < K1P * K1P; idx += 256) {
        int i = idx / K1P, j = idx - i * K1P;
        float e = s2[i] + t2[j] + ba;
        e = e > 0.f ? e : 0.f;
        atts[i * 57 + j] = expf(e) * adjb[idx];
    }
    __syncthreads();
    if (t < K1P) {
        float s = 0.f;
        for (int j = 0; j < K1P; j++) s += atts[t * 57 + j];
        invr[t] = 1.f / s;
    }
    __syncthreads();

    // out2 = att_norm @ h2 + h2, relu; accumulate pool2 scores
    float acc2[7][4];
    #pragma unroll
    for (int r = 0; r < 7; r++) { acc2[r][0]=0.f; acc2[r][1]=0.f; acc2[r][2]=0.f; acc2[r][3]=0.f; }
    #pragma unroll 2
    for (int j = 0; j < K1P; j++) {
        float4 hv = *(const float4*)&h2s[j * 132 + tx * 4];
        #pragma unroll
        for (int r = 0; r < 7; r++) {
            float a = atts[(ty * 7 + r) * 57 + j];
            acc2[r][0] = fmaf(a, hv.x, acc2[r][0]);
            acc2[r][1] = fmaf(a, hv.y, acc2[r][1]);
            acc2[r][2] = fmaf(a, hv.z, acc2[r][2]);
            acc2[r][3] = fmaf(a, hv.w, acc2[r][3]);
        }
    }
    {
        const float* wpp = Wpool2 + tx * 4;
        float w0 = wpp[0], w1 = wpp[1], w2 = wpp[2], w3 = wpp[3];
        #pragma unroll
        for (int r = 0; r < 7; r++) {
            int i = ty * 7 + r;
            float ir = invr[i];
            float4 hself = *(const float4*)&h2s[i * 132 + tx * 4];
            float v0 = fmaxf(fmaf(acc2[r][0], ir, hself.x), 0.f);
            float v1 = fmaxf(fmaf(acc2[r][1], ir, hself.y), 0.f);
            float v2 = fmaxf(fmaf(acc2[r][2], ir, hself.z), 0.f);
            float v3 = fmaxf(fmaf(acc2[r][3], ir, hself.w), 0.f);
            h2r[i * 132 + tx * 4 + 0] = v0;
            h2r[i * 132 + tx * 4 + 1] = v1;
            h2r[i * 132 + tx * 4 + 2] = v2;
            h2r[i * 132 + tx * 4 + 3] = v3;
            atomicAdd(&sc2[i], v0 * w0 + v1 * w1 + v2 * w2 + v3 * w3);
        }
    }
    __syncthreads();

    // top-28 of 56 (pad to 64)
    if (t < 64) {
        if (t < K1P) {
            skey[t] = 1.f / (1.f + expf(-(sc2[t] + bpool2[0])));
            sidx[t] = t;
        } else { skey[t] = -1.f; sidx[t] = t; }
    }
    __syncthreads();
    for (int k = 2; k <= 64; k <<= 1) {
        for (int j = k >> 1; j > 0; j >>= 1) {
            if (t < 64) {
                int l = t ^ j;
                if (l > t) {
                    float a = skey[t], c = skey[l];
                    int ia = sidx[t], ib = sidx[l];
                    bool before = (a > c) || (a == c && ia < ib);
                    bool up = ((t & k) == 0);
                    if (up ? !before : before) {
                        skey[t] = c; skey[l] = a;
                        sidx[t] = ib; sidx[l] = ia;
                    }
                }
            }
            __syncthreads();
        }
    }

    // mean over top-28 (scaled by vals)
    if (t < L2D) {
        float s = 0.f;
        #pragma unroll 4
        for (int m = 0; m < K2P; m++)
            s += h2r[sidx[m] * 132 + t] * skey[m];
        mvec[t] = s * (1.f / (float)K2P);
    }
    __syncthreads();
    // FC1 + relu
    if (t < L3D) {
        float s = bfc1[t];
        #pragma unroll 8
        for (int d = 0; d < L2D; d++) s = fmaf(mvec[d], Wfc1[t * L2D + d], s);
        y1[t] = fmaxf(s, 0.f);
    }
    __syncthreads();
    // FC2
    if (t == 0) {
        float s = bfc2[0];
        for (int o = 0; o < L3D; o++) s = fmaf(y1[o], Wfc2[o], s);
        out[b] = s;
    }
}

// ---------------- launch ----------------
extern "C" void kernel_launch(void* const* d_in, const int* in_sizes, int n_in,
                              void* d_out, int out_size) {
    const float* x      = (const float*)d_in[0];
    const float* Wp1    = (const float*)d_in[1];
    const float* bp1    = (const float*)d_in[2];
    const float* wa1    = (const float*)d_in[3];
    const float* wb1    = (const float*)d_in[4];
    const float* ba1    = (const float*)d_in[5];
    const float* Wpool1 = (const float*)d_in[6];
    const float* bpool1 = (const float*)d_in[7];
    const float* Wp2    = (const float*)d_in[8];
    const float* bp2    = (const float*)d_in[9];
    const float* wa2    = (const float*)d_in[10];
    const float* wb2    = (const float*)d_in[11];
    const float* ba2    = (const float*)d_in[12];
    const float* Wpool2 = (const float*)d_in[13];
    const float* bpool2 = (const float*)d_in[14];
    const float* Wfc1   = (const float*)d_in[15];
    const float* bfc1   = (const float*)d_in[16];
    const float* Wfc2   = (const float*)d_in[17];
    const float* bfc2   = (const float*)d_in[18];
    float* out = (float*)d_out;

    size_t smem2 = (size_t)K2_FLOATS * sizeof(float);
    size_t smem3 = (size_t)K3_FLOATS * sizeof(float);
    cudaFuncSetAttribute(k_gat1, cudaFuncAttributeMaxDynamicSharedMemorySize, (int)smem2);
    cudaFuncSetAttribute(k_gat2, cudaFuncAttributeMaxDynamicSharedMemorySize, (int)smem3);

    k_pre<<<1, 256>>>(Wp1, bp1, wa1, wb1, ba1, Wp2);
    k_gat1<<<BATCH, 256, smem2>>>(x, Wpool1, bpool1);
    k_gat2<<<BATCH, 256, smem3>>>(bp2, wa2, wb2, ba2, Wpool2, bpool2,
                                  Wfc1, bfc1, Wfc2, bfc2, out);
}

// round 3
// speedup vs baseline: 1.0296x; 1.0296x over previous
#include <cuda_runtime.h>
#include <math.h>
#include <stdint.h>

#define NODE 112
#define L1D 256
#define L2D 128
#define L3D 64
#define BATCH 2048
#define K1P 56
#define K2P 28

// ---------------- f32x2 packed-FMA helpers (sm_103a FFMA2) ----------------
__device__ __forceinline__ void fma2(uint64_t& d, uint64_t a, uint64_t b) {
    asm("fma.rn.f32x2 %0, %1, %2, %0;" : "+l"(d) : "l"(a), "l"(b));
}
__device__ __forceinline__ uint64_t dup2(float a) {
    uint64_t r; asm("mov.b64 %0, {%1, %1};" : "=l"(r) : "f"(a)); return r;
}
__device__ __forceinline__ float2 unpk(uint64_t v) {
    float2 r; asm("mov.b64 {%0, %1}, %2;" : "=f"(r.x), "=f"(r.y) : "l"(v)); return r;
}

// ---------------- global scratch (no allocations allowed) ----------------
__device__ float g_H0[NODE * L1D];        // projected identity features (batch-indep)
__device__ float g_E1[NODE * NODE];       // exp(relu(s_i + t_j + ba1))   (batch-indep)
__device__ float g_Wp2T[L1D * L2D];       // Wp2 transposed [d][o]
__device__ float g_h1[(size_t)BATCH * NODE * L1D];   // GAT1 output
__device__ float g_hp[(size_t)BATCH * K1P * L1D];    // pooled hidden
__device__ float g_adj[(size_t)BATCH * K1P * K1P];   // pooled normalized adj

// ---------------- K1: batch-independent precompute (1 CTA, 512 thr) -------
__global__ void k_pre(const float* __restrict__ Wp1, const float* __restrict__ bp1,
                      const float* __restrict__ wa1, const float* __restrict__ wb1,
                      const float* __restrict__ ba1, const float* __restrict__ Wp2) {
    __shared__ float s1[NODE], t1[NODE];
    int t = threadIdx.x;
    // H0[n][o] = Wp1[o][n] + bp1[o] : one thread per o, coalesced writes,
    // per-thread-sequential reads hit L1 after first pass (Wp1 = 50 KB).
    if (t < 256) {
        int o = t; float bo = bp1[o];
        #pragma unroll 4
        for (int n = 0; n < NODE; n++) g_H0[n * L1D + o] = Wp1[o * NODE + n] + bo;
    } else if (t < 384) {
        int o = t - 256;   // Wp2T[d][o] = Wp2[o][d]
        #pragma unroll 4
        for (int d = 0; d < L1D; d++) g_Wp2T[d * L2D + o] = Wp2[o * L1D + d];
    }
    __syncthreads();
    if (t < NODE) {
        float ss = 0.f, tt = 0.f;
        for (int o = 0; o < L1D; o++) {
            float h = g_H0[t * L1D + o];
            ss = fmaf(h, wa1[o], ss);
            tt = fmaf(h, wb1[o], tt);
        }
        s1[t] = ss; t1[t] = tt;
    }
    __syncthreads();
    float ba = ba1[0];
    for (int idx = t; idx < NODE * NODE; idx += blockDim.x) {
        int i = idx / NODE, j = idx - i * NODE;
        float e = s1[i] + t1[j] + ba;
        e = e > 0.f ? e : 0.f;
        g_E1[idx] = expf(e);
    }
}

// ---------------- K2: GAT1 + pool1 (one CTA per batch, 256 threads) --------
#define K2_WS     (NODE * 113)
#define K2_H0T    (K2_WS + NODE * 64)
#define K2_INVR   (K2_H0T + NODE)
#define K2_SCR    (K2_INVR + NODE)
#define K2_SKEY   (K2_SCR + 128)
#define K2_SIDX   (K2_SKEY + 128)          // ints
#define K2_ADJB   (K2_SIDX + K1P * 57)
#define K2_FLOATS (K2_ADJB)

__global__ void __launch_bounds__(256, 2)
k_gat1(const float* __restrict__ x, const float* __restrict__ Wpool1,
       const float* __restrict__ bpool1) {
    extern __shared__ float sm[];
    float* Ws   = sm;
    float* H0t  = sm + K2_WS;
    float* invr = sm + K2_H0T;
    float* scr  = sm + K2_INVR;
    float* skey = sm + K2_SCR;
    int*   sidx = (int*)(sm + K2_SKEY);
    float* adjb = sm + K2_SIDX;

    int b = blockIdx.x;
    int t = threadIdx.x;
    const float* xb = x + (size_t)b * NODE * NODE;

    // W = E1 .* x[b]
    for (int idx = t; idx < NODE * NODE; idx += 256) {
        int i = idx / NODE, j = idx - i * NODE;
        Ws[i * 113 + j] = g_E1[idx] * xb[idx];
    }
    if (t < NODE) scr[t] = 0.f;
    __syncthreads();
    if (t < NODE) {
        float s = 0.f;
        #pragma unroll 8
        for (int j = 0; j < NODE; j++) s += Ws[t * 113 + j];
        invr[t] = 1.f / s;
    }
    __syncthreads();

    int tx = t & 15, ty = t >> 4;       // cols tx*4..+3 (of 64), rows ty*7..+6
    float* h1b = g_h1 + (size_t)b * NODE * L1D;
    float wc0, wc1, wc2, wc3;

    for (int ct = 0; ct < 4; ct++) {
        for (int idx = t; idx < NODE * 64; idx += 256) {
            int j = idx >> 6, c = idx & 63;
            H0t[idx] = g_H0[j * L1D + ct * 64 + c];
        }
        __syncthreads();
        {
            const float* wp = Wpool1 + ct * 64 + tx * 4;
            wc0 = wp[0]; wc1 = wp[1]; wc2 = wp[2]; wc3 = wp[3];
        }
        uint64_t acc[7][2];
        #pragma unroll
        for (int r = 0; r < 7; r++) { acc[r][0] = 0ull; acc[r][1] = 0ull; }

        #pragma unroll 2
        for (int j = 0; j < NODE; j++) {
            ulonglong2 bv = *(const ulonglong2*)&H0t[j * 64 + tx * 4];
            #pragma unroll
            for (int r = 0; r < 7; r++) {
                uint64_t ap = dup2(Ws[(ty * 7 + r) * 113 + j]);
                fma2(acc[r][0], ap, bv.x);
                fma2(acc[r][1], ap, bv.y);
            }
        }
        #pragma unroll
        for (int r = 0; r < 7; r++) {
            int i = ty * 7 + r;
            float ir = invr[i];
            float4 h0v = *(const float4*)&H0t[i * 64 + tx * 4];
            float2 a01 = unpk(acc[r][0]);
            float2 a23 = unpk(acc[r][1]);
            float4 v;
            v.x = fmaxf(fmaf(a01.x, ir, h0v.x), 0.f);
            v.y = fmaxf(fmaf(a01.y, ir, h0v.y), 0.f);
            v.z = fmaxf(fmaf(a23.x, ir, h0v.z), 0.f);
            v.w = fmaxf(fmaf(a23.y, ir, h0v.w), 0.f);
            *(float4*)&h1b[i * L1D + ct * 64 + tx * 4] = v;
            float sp = v.x * wc0 + v.y * wc1 + v.z * wc2 + v.w * wc3;
            atomicAdd(&scr[i], sp);
        }
        __syncthreads();
    }

    // pool scores -> sigmoid -> bitonic top-56 (pad to 128)
    if (t < 128) {
        if (t < NODE) {
            skey[t] = 1.f / (1.f + expf(-(scr[t] + bpool1[0])));
            sidx[t] = t;
        } else { skey[t] = -1.f; sidx[t] = t; }
    }
    __syncthreads();
    for (int k = 2; k <= 128; k <<= 1) {
        for (int j = k >> 1; j > 0; j >>= 1) {
            if (t < 128) {
                int l = t ^ j;
                if (l > t) {
                    float a = skey[t], c = skey[l];
                    int ia = sidx[t], ib = sidx[l];
                    bool before = (a > c) || (a == c && ia < ib);
                    bool up = ((t & k) == 0);
                    if (up ? !before : before) {
                        skey[t] = c; skey[l] = a;
                        sidx[t] = ib; sidx[l] = ia;
                    }
                }
            }
            __syncthreads();
        }
    }

    // gather pooled hidden (scaled by score)
    float* hpb = g_hp + (size_t)b * K1P * L1D;
    for (int idx = t; idx < K1P * L1D; idx += 256) {
        int m = idx >> 8, c = idx & 255;
        hpb[idx] = h1b[sidx[m] * L1D + c] * skey[m];
    }
    // pooled adjacency, row-normalized
    for (int idx = t; idx < K1P * K1P; idx += 256) {
        int i = idx / K1P, j = idx - i * K1P;
        adjb[i * 57 + j] = xb[sidx[i] * NODE + sidx[j]];
    }
    __syncthreads();
    if (t < K1P) {
        float s = 0.f;
        for (int j = 0; j < K1P; j++) s += adjb[t * 57 + j];
        invr[t] = 1.f / s;
    }
    __syncthreads();
    float* adjo = g_adj + (size_t)b * K1P * K1P;
    for (int idx = t; idx < K1P * K1P; idx += 256) {
        int i = idx / K1P, j = idx - i * K1P;
        adjo[idx] = adjb[i * 57 + j] * invr[i];
    }
}

// ---------------- K3: GAT2 + pool2 + mean + FC head ----------------
#define K3_HS    (K1P * L1D)                  // 14336
#define K3_W2S   (K3_HS + 64 * L2D)           // +8192
#define K3_H2S   (K3_W2S + K1P * 132)         // +7392
#define K3_H2R   (K3_H2S + K1P * 132)         // +7392
#define K3_ATT   (K3_H2R + K1P * 57)          // +3192
#define K3_S2    (K3_ATT + K1P)
#define K3_T2    (K3_S2 + K1P)
#define K3_SC2   (K3_T2 + K1P)
#define K3_INVR  (K3_SC2 + K1P)
#define K3_SKEY  (K3_INVR + 64)
#define K3_SIDX  (K3_SKEY + 64)               // ints
#define K3_MVEC  (K3_SIDX + L2D)
#define K3_Y1    (K3_MVEC + L3D)
#define K3_FLOATS (K3_Y1)

__global__ void __launch_bounds__(256, 1)
k_gat2(const float* __restrict__ bp2, const float* __restrict__ wa2,
       const float* __restrict__ wb2, const float* __restrict__ ba2,
       const float* __restrict__ Wpool2, const float* __restrict__ bpool2,
       const float* __restrict__ Wfc1, const float* __restrict__ bfc1,
       const float* __restrict__ Wfc2, const float* __restrict__ bfc2,
       float* __restrict__ out) {
    extern __shared__ float sm[];
    float* Hs   = sm;
    float* W2s  = sm + K3_HS;
    float* h2s  = sm + K3_W2S;
    float* h2r  = sm + K3_H2S;
    float* atts = sm + K3_H2R;
    float* s2   = sm + K3_ATT;
    float* t2   = sm + K3_S2;
    float* sc2  = sm + K3_T2;
    float* invr = sm + K3_SC2;
    float* skey = sm + K3_INVR;
    int*   sidx = (int*)(sm + K3_SKEY);
    float* mvec = sm + K3_SIDX;
    float* y1   = sm + K3_MVEC;

    int b = blockIdx.x;
    int t = threadIdx.x;

    for (int idx = t; idx < K1P * L1D; idx += 256)
        Hs[idx] = g_hp[(size_t)b * K1P * L1D + idx];
    if (t < K1P) { s2[t] = 0.f; t2[t] = 0.f; sc2[t] = 0.f; }
    __syncthreads();

    int tx = t & 31, ty = t >> 5;   // cols tx*4..+3 (of 128), rows ty*7..+6 (of 56)

    // h2 = Hs @ Wp2^T + bp2  (56x256 @ 256x128)
    uint64_t acc[7][2];
    #pragma unroll
    for (int r = 0; r < 7; r++) { acc[r][0] = 0ull; acc[r][1] = 0ull; }
    for (int dt = 0; dt < 4; dt++) {
        for (int idx = t; idx < 64 * L2D; idx += 256)
            W2s[idx] = g_Wp2T[(dt * 64) * L2D + idx];
        __syncthreads();
        #pragma unroll 2
        for (int d = 0; d < 64; d++) {
            ulonglong2 wv = *(const ulonglong2*)&W2s[d * L2D + tx * 4];
            #pragma unroll
            for (int r = 0; r < 7; r++) {
                uint64_t ap = dup2(Hs[(ty * 7 + r) * L1D + dt * 64 + d]);
                fma2(acc[r][0], ap, wv.x);
                fma2(acc[r][1], ap, wv.y);
            }
        }
        __syncthreads();
    }
    {
        const float* bpp = bp2 + tx * 4;
        float b0 = bpp[0], b1 = bpp[1], b2 = bpp[2], b3 = bpp[3];
        const float* wap = wa2 + tx * 4;
        const float* wbp = wb2 + tx * 4;
        float wa0=wap[0], wa1v=wap[1], wa2v=wap[2], wa3=wap[3];
        float wb0=wbp[0], wb1v=wbp[1], wb2v=wbp[2], wb3=wbp[3];
        #pragma unroll
        for (int r = 0; r < 7; r++) {
            int i = ty * 7 + r;
            float2 a01 = unpk(acc[r][0]);
            float2 a23 = unpk(acc[r][1]);
            float v0 = a01.x + b0, v1 = a01.y + b1;
            float v2 = a23.x + b2, v3 = a23.y + b3;
            h2s[i * 132 + tx * 4 + 0] = v0;
            h2s[i * 132 + tx * 4 + 1] = v1;
            h2s[i * 132 + tx * 4 + 2] = v2;
            h2s[i * 132 + tx * 4 + 3] = v3;
            atomicAdd(&s2[i], v0 * wa0 + v1 * wa1v + v2 * wa2v + v3 * wa3);
            atomicAdd(&t2[i], v0 * wb0 + v1 * wb1v + v2 * wb2v + v3 * wb3);
        }
    }
    __syncthreads();

    // attention weights
    float ba = ba2[0];
    const float* adjb = g_adj + (size_t)b * K1P * K1P;
    for (int idx = t; idx < K1P * K1P; idx += 256) {
        int i = idx / K1P, j = idx - i * K1P;
        float e = s2[i] + t2[j] + ba;
        e = e > 0.f ? e : 0.f;
        atts[i * 57 + j] = expf(e) * adjb[idx];
    }
    __syncthreads();
    if (t < K1P) {
        float s = 0.f;
        for (int j = 0; j < K1P; j++) s += atts[t * 57 + j];
        invr[t] = 1.f / s;
    }
    __syncthreads();

    // out2 = att_norm @ h2 + h2, relu; accumulate pool2 scores
    uint64_t acc2[7][2];
    #pragma unroll
    for (int r = 0; r < 7; r++) { acc2[r][0] = 0ull; acc2[r][1] = 0ull; }
    #pragma unroll 2
    for (int j = 0; j < K1P; j++) {
        ulonglong2 hv = *(const ulonglong2*)&h2s[j * 132 + tx * 4];
        #pragma unroll
        for (int r = 0; r < 7; r++) {
            uint64_t ap = dup2(atts[(ty * 7 + r) * 57 + j]);
            fma2(acc2[r][0], ap, hv.x);
            fma2(acc2[r][1], ap, hv.y);
        }
    }
    {
        const float* wpp = Wpool2 + tx * 4;
        float w0 = wpp[0], w1 = wpp[1], w2 = wpp[2], w3 = wpp[3];
        #pragma unroll
        for (int r = 0; r < 7; r++) {
            int i = ty * 7 + r;
            float ir = invr[i];
            float4 hself = *(const float4*)&h2s[i * 132 + tx * 4];
            float2 a01 = unpk(acc2[r][0]);
            float2 a23 = unpk(acc2[r][1]);
            float v0 = fmaxf(fmaf(a01.x, ir, hself.x), 0.f);
            float v1 = fmaxf(fmaf(a01.y, ir, hself.y), 0.f);
            float v2 = fmaxf(fmaf(a23.x, ir, hself.z), 0.f);
            float v3 = fmaxf(fmaf(a23.y, ir, hself.w), 0.f);
            h2r[i * 132 + tx * 4 + 0] = v0;
            h2r[i * 132 + tx * 4 + 1] = v1;
            h2r[i * 132 + tx * 4 + 2] = v2;
            h2r[i * 132 + tx * 4 + 3] = v3;
            atomicAdd(&sc2[i], v0 * w0 + v1 * w1 + v2 * w2 + v3 * w3);
        }
    }
    __syncthreads();

    // top-28 of 56 (pad to 64)
    if (t < 64) {
        if (t < K1P) {
            skey[t] = 1.f / (1.f + expf(-(sc2[t] + bpool2[0])));
            sidx[t] = t;
        } else { skey[t] = -1.f; sidx[t] = t; }
    }
    __syncthreads();
    for (int k = 2; k <= 64; k <<= 1) {
        for (int j = k >> 1; j > 0; j >>= 1) {
            if (t < 64) {
                int l = t ^ j;
                if (l > t) {
                    float a = skey[t], c = skey[l];
                    int ia = sidx[t], ib = sidx[l];
                    bool before = (a > c) || (a == c && ia < ib);
                    bool up = ((t & k) == 0);
                    if (up ? !before : before) {
                        skey[t] = c; skey[l] = a;
                        sidx[t] = ib; sidx[l] = ia;
                    }
                }
            }
            __syncthreads();
        }
    }

    // mean over top-28 (scaled by vals)
    if (t < L2D) {
        float s = 0.f;
        #pragma unroll 4
        for (int m = 0; m < K2P; m++)
            s += h2r[sidx[m] * 132 + t] * skey[m];
        mvec[t] = s * (1.f / (float)K2P);
    }
    __syncthreads();
    // FC1 + relu
    if (t < L3D) {
        float s = bfc1[t];
        #pragma unroll 8
        for (int d = 0; d < L2D; d++) s = fmaf(mvec[d], Wfc1[t * L2D + d], s);
        y1[t] = fmaxf(s, 0.f);
    }
    __syncthreads();
    // FC2
    if (t == 0) {
        float s = bfc2[0];
        for (int o = 0; o < L3D; o++) s = fmaf(y1[o], Wfc2[o], s);
        out[b] = s;
    }
}

// ---------------- launch ----------------
extern "C" void kernel_launch(void* const* d_in, const int* in_sizes, int n_in,
                              void* d_out, int out_size) {
    const float* x      = (const float*)d_in[0];
    const float* Wp1    = (const float*)d_in[1];
    const float* bp1    = (const float*)d_in[2];
    const float* wa1    = (const float*)d_in[3];
    const float* wb1    = (const float*)d_in[4];
    const float* ba1    = (const float*)d_in[5];
    const float* Wpool1 = (const float*)d_in[6];
    const float* bpool1 = (const float*)d_in[7];
    const float* Wp2    = (const float*)d_in[8];
    const float* bp2    = (const float*)d_in[9];
    const float* wa2    = (const float*)d_in[10];
    const float* wb2    = (const float*)d_in[11];
    const float* ba2    = (const float*)d_in[12];
    const float* Wpool2 = (const float*)d_in[13];
    const float* bpool2 = (const float*)d_in[14];
    const float* Wfc1   = (const float*)d_in[15];
    const float* bfc1   = (const float*)d_in[16];
    const float* Wfc2   = (const float*)d_in[17];
    const float* bfc2   = (const float*)d_in[18];
    float* out = (float*)d_out;

    size_t smem2 = (size_t)K2_FLOATS * sizeof(float);
    size_t smem3 = (size_t)K3_FLOATS * sizeof(float);
    cudaFuncSetAttribute(k_gat1, cudaFuncAttributeMaxDynamicSharedMemorySize, (int)smem2);
    cudaFuncSetAttribute(k_gat2, cudaFuncAttributeMaxDynamicSharedMemorySize, (int)smem3);

    k_pre<<<1, 512>>>(Wp1, bp1, wa1, wb1, ba1, Wp2);
    k_gat1<<<BATCH, 256, smem2>>>(x, Wpool1, bpool1);
    k_gat2<<<BATCH, 256, smem3>>>(bp2, wa2, wb2, ba2, Wpool2, bpool2,
                                  Wfc1, bfc1, Wfc2, bfc2, out);
}

// round 5
// speedup vs baseline: 1.1907x; 1.1564x over previous
#include <cuda_runtime.h>
#include <math.h>
#include <stdint.h>

#define NODE 112
#define L1D 256
#define L2D 128
#define L3D 64
#define BATCH 2048
#define K1P 56
#define K2P 28

// ---------------- f32x2 packed-FMA helpers (sm_103a FFMA2) ----------------
__device__ __forceinline__ void fma2(uint64_t& d, uint64_t a, uint64_t b) {
    asm("fma.rn.f32x2 %0, %1, %2, %0;" : "+l"(d) : "l"(a), "l"(b));
}
__device__ __forceinline__ float psum(uint64_t v) {
    float2 r; asm("mov.b64 {%0, %1}, %2;" : "=f"(r.x), "=f"(r.y) : "l"(v));
    return r.x + r.y;
}
__device__ __forceinline__ uint64_t lds64(const float* p) {
    return *(const uint64_t*)p;
}

// ---------------- global scratch ----------------
__device__ float g_H0[NODE * L1D];            // row-major (unused in hot loops, kept for clarity)
__device__ float g_H0P[NODE * L1D];           // k-pair interleaved: [n/2][o][2]
__device__ float g_E1[NODE * NODE];
__device__ float g_Wp2P[L1D * L2D];           // k-pair interleaved: [d/2][o][2]
__device__ float g_h1[(size_t)BATCH * NODE * L1D];
__device__ float g_hp[(size_t)BATCH * K1P * L1D];
__device__ float g_adj[(size_t)BATCH * K1P * K1P];
__device__ float g_dummy;

// ---------------- K-preA: transposes/interleaves (32 CTAs) ----------------
__global__ void k_preA(const float* __restrict__ Wp1, const float* __restrict__ bp1,
                       const float* __restrict__ Wp2) {
    int t = blockIdx.x * blockDim.x + threadIdx.x;
    int NT = gridDim.x * blockDim.x;
    for (int idx = t; idx < NODE * L1D; idx += NT) {
        int o = idx / NODE, n = idx - o * NODE;       // Wp1 read coalesced over n
        float v = Wp1[idx] + bp1[o];
        g_H0[n * L1D + o] = v;
        g_H0P[(n >> 1) * (2 * L1D) + o * 2 + (n & 1)] = v;
    }
    for (int idx = t; idx < L1D * L2D; idx += NT) {
        int o = idx >> 8, d = idx & 255;              // Wp2 read coalesced over d
        g_Wp2P[(d >> 1) * (2 * L2D) + o * 2 + (d & 1)] = Wp2[idx];
    }
}

// ---------------- K-preB: attention table E1 (1 CTA) ----------------
__global__ void k_preB(const float* __restrict__ wa1, const float* __restrict__ wb1,
                       const float* __restrict__ ba1) {
    __shared__ float s1[NODE], t1[NODE];
    int t = threadIdx.x;
    if (t < NODE) {
        float ss = 0.f, tt = 0.f;
        #pragma unroll 4
        for (int o = 0; o < L1D; o++) {
            float h = g_H0[t * L1D + o];
            ss = fmaf(h, wa1[o], ss);
            tt = fmaf(h, wb1[o], tt);
        }
        s1[t] = ss; t1[t] = tt;
    }
    __syncthreads();
    float ba = ba1[0];
    for (int idx = t; idx < NODE * NODE; idx += blockDim.x) {
        int i = idx / NODE, j = idx - i * NODE;
        float e = s1[i] + t1[j] + ba;
        e = e > 0.f ? e : 0.f;
        g_E1[idx] = expf(e);
    }
}

__global__ void k_tail() { if (threadIdx.x == 0) g_dummy = 1.f; }

// ---------------- K2: GAT1 + pool1 (one CTA per batch, 256 threads) --------
// smem (floats): Ws[112*114] | H0p[56*128] | invr[112] | scr[112] | skey[128] | sidx[128] | adjb[56*57]
#define G1_WS    (NODE * 114)
#define G1_H0P   (G1_WS + 56 * 128)
#define G1_INVR  (G1_H0P + NODE)
#define G1_SCR   (G1_INVR + NODE)
#define G1_SKEY  (G1_SCR + 128)
#define G1_SIDX  (G1_SKEY + 128)
#define G1_ADJB  (G1_SIDX + K1P * 57)
#define G1_FLOATS (G1_ADJB)

__global__ void __launch_bounds__(256, 2)
k_gat1(const float* __restrict__ x, const float* __restrict__ Wpool1,
       const float* __restrict__ bpool1) {
    extern __shared__ float sm[];
    float* Ws   = sm;
    float* H0p  = sm + G1_WS;
    float* invr = sm + G1_H0P;
    float* scr  = sm + G1_INVR;
    float* skey = sm + G1_SCR;
    int*   sidx = (int*)(sm + G1_SKEY);
    float* adjb = sm + G1_SIDX;

    int b = blockIdx.x;
    int t = threadIdx.x;
    const float* xb = x + (size_t)b * NODE * NODE;

    for (int idx = t; idx < NODE * NODE; idx += 256) {
        int i = idx / NODE, j = idx - i * NODE;
        Ws[i * 114 + j] = g_E1[idx] * xb[idx];
    }
    if (t < NODE) scr[t] = 0.f;
    __syncthreads();
    if (t < NODE) {
        float s = 0.f;
        #pragma unroll 8
        for (int j = 0; j < NODE; j++) s += Ws[t * 114 + j];
        invr[t] = 1.f / s;
    }
    __syncthreads();

    int tx = t & 15, ty = t >> 4;
    int row0 = ty * 7;
    float* h1b = g_h1 + (size_t)b * NODE * L1D;

    for (int ct = 0; ct < 4; ct++) {
        // load k-pair-interleaved H0 tile: cols [ct*64, ct*64+64)
        for (int idx = t; idx < 56 * 128; idx += 256) {
            int jp = idx >> 7, rem = idx & 127;
            H0p[idx] = g_H0P[jp * 512 + ct * 128 + rem];
        }
        __syncthreads();
        float wc0, wc1, wc2, wc3;
        {
            const float* wp = Wpool1 + ct * 64 + tx * 4;
            wc0 = wp[0]; wc1 = wp[1]; wc2 = wp[2]; wc3 = wp[3];
        }
        uint64_t acc[7][4];
        #pragma unroll
        for (int r = 0; r < 7; r++) { acc[r][0]=0; acc[r][1]=0; acc[r][2]=0; acc[r][3]=0; }

        #pragma unroll 2
        for (int jp = 0; jp < 56; jp++) {
            ulonglong2 bv0 = *(const ulonglong2*)&H0p[jp * 128 + tx * 8];
            ulonglong2 bv1 = *(const ulonglong2*)&H0p[jp * 128 + tx * 8 + 4];
            #pragma unroll
            for (int r = 0; r < 7; r++) {
                uint64_t ap = lds64(&Ws[(row0 + r) * 114 + jp * 2]);
                fma2(acc[r][0], ap, bv0.x);
                fma2(acc[r][1], ap, bv0.y);
                fma2(acc[r][2], ap, bv1.x);
                fma2(acc[r][3], ap, bv1.y);
            }
        }
        #pragma unroll
        for (int r = 0; r < 7; r++) {
            int i = row0 + r;
            float ir = invr[i];
            int hb = (i >> 1) * 128 + (i & 1);
            float4 v;
            v.x = fmaxf(fmaf(psum(acc[r][0]), ir, H0p[hb + (tx*4+0)*2]), 0.f);
            v.y = fmaxf(fmaf(psum(acc[r][1]), ir, H0p[hb + (tx*4+1)*2]), 0.f);
            v.z = fmaxf(fmaf(psum(acc[r][2]), ir, H0p[hb + (tx*4+2)*2]), 0.f);
            v.w = fmaxf(fmaf(psum(acc[r][3]), ir, H0p[hb + (tx*4+3)*2]), 0.f);
            *(float4*)&h1b[i * L1D + ct * 64 + tx * 4] = v;
            atomicAdd(&scr[i], v.x*wc0 + v.y*wc1 + v.z*wc2 + v.w*wc3);
        }
        __syncthreads();
    }

    // sigmoid + bitonic top-56 (pad 128)
    if (t < 128) {
        if (t < NODE) {
            skey[t] = 1.f / (1.f + expf(-(scr[t] + bpool1[0])));
            sidx[t] = t;
        } else { skey[t] = -1.f; sidx[t] = t; }
    }
    __syncthreads();
    for (int k = 2; k <= 128; k <<= 1) {
        for (int j = k >> 1; j > 0; j >>= 1) {
            if (t < 128) {
                int l = t ^ j;
                if (l > t) {
                    float a = skey[t], c = skey[l];
                    int ia = sidx[t], ib = sidx[l];
                    bool before = (a > c) || (a == c && ia < ib);
                    if (((t & k) == 0) ? !before : before) {
                        skey[t] = c; skey[l] = a;
                        sidx[t] = ib; sidx[l] = ia;
                    }
                }
            }
            __syncthreads();
        }
    }

    float* hpb = g_hp + (size_t)b * K1P * L1D;
    for (int idx = t; idx < K1P * L1D; idx += 256) {
        int m = idx >> 8, c = idx & 255;
        hpb[idx] = h1b[sidx[m] * L1D + c] * skey[m];
    }
    for (int idx = t; idx < K1P * K1P; idx += 256) {
        int i = idx / K1P, j = idx - i * K1P;
        adjb[i * 57 + j] = xb[sidx[i] * NODE + sidx[j]];
    }
    __syncthreads();
    if (t < K1P) {
        float s = 0.f;
        for (int j = 0; j < K1P; j++) s += adjb[t * 57 + j];
        invr[t] = 1.f / s;
    }
    __syncthreads();
    float* adjo = g_adj + (size_t)b * K1P * K1P;
    for (int idx = t; idx < K1P * K1P; idx += 256) {
        int i = idx / K1P, j = idx - i * K1P;
        adjo[idx] = adjb[i * 57 + j] * invr[i];
    }
}

// ---------------- K3: GAT2 + pool2 + mean + FC head (occ 2) ----------------
// smem (floats): Hst[56*32] | W2p[16*256] | h2p[28*256] | h2r[56*132] | atts[56*58]
//                | s2[56] t2[56] sc2[56] invr[64] skey[64] sidx[64] mvec[128] y1[64]
#define G2_HST   (56 * 32)
#define G2_W2P   (G2_HST + 16 * 256)
#define G2_H2P   (G2_W2P + 28 * 256)
#define G2_H2R   (G2_H2P + K1P * 132)
#define G2_ATT   (G2_H2R + K1P * 58)
#define G2_S2    (G2_ATT + K1P)
#define G2_T2    (G2_S2 + K1P)
#define G2_SC2   (G2_T2 + K1P)
#define G2_INVR  (G2_SC2 + 64)
#define G2_SKEY  (G2_INVR + 64)
#define G2_SIDX  (G2_SKEY + 64)
#define G2_MVEC  (G2_SIDX + 128)
#define G2_Y1    (G2_MVEC + 64)
#define G2_FLOATS (G2_Y1)

__global__ void __launch_bounds__(256, 2)
k_gat2(const float* __restrict__ bp2, const float* __restrict__ wa2,
       const float* __restrict__ wb2, const float* __restrict__ ba2,
       const float* __restrict__ Wpool2, const float* __restrict__ bpool2,
       const float* __restrict__ Wfc1, const float* __restrict__ bfc1,
       const float* __restrict__ Wfc2, const float* __restrict__ bfc2,
       float* __restrict__ out) {
    extern __shared__ float sm[];
    float* Hst  = sm;
    float* W2p  = sm + G2_HST;
    float* h2p  = sm + G2_W2P;
    float* h2r  = sm + G2_H2P;
    float* atts = sm + G2_H2R;
    float* s2   = sm + G2_ATT;
    float* t2   = sm + G2_S2;
    float* sc2  = sm + G2_T2;
    float* invr = sm + G2_SC2;
    float* skey = sm + G2_INVR;
    int*   sidx = (int*)(sm + G2_SKEY);
    float* mvec = sm + G2_SIDX;
    float* y1   = sm + G2_MVEC;

    int b = blockIdx.x;
    int t = threadIdx.x;
    const float* hpb = g_hp + (size_t)b * K1P * L1D;

    if (t < K1P) { s2[t] = 0.f; t2[t] = 0.f; sc2[t] = 0.f; }

    int tx = t & 31, ty = t >> 5;
    int row0 = ty * 7;

    // GEMM1: h2 = Hs @ Wp2^T + bp2  (56x256 @ 256x128), K tiled by 32
    uint64_t acc[7][4];
    #pragma unroll
    for (int r = 0; r < 7; r++) { acc[r][0]=0; acc[r][1]=0; acc[r][2]=0; acc[r][3]=0; }
    for (int dt = 0; dt < 8; dt++) {
        for (int idx = t; idx < 56 * 32; idx += 256) {
            int i = idx >> 5, dd = idx & 31;
            Hst[idx] = hpb[i * L1D + dt * 32 + dd];
        }
        for (int idx = t; idx < 16 * 256; idx += 256)
            W2p[idx] = g_Wp2P[dt * 4096 + idx];
        __syncthreads();
        #pragma unroll 2
        for (int dp = 0; dp < 16; dp++) {
            ulonglong2 bv0 = *(const ulonglong2*)&W2p[dp * 256 + tx * 8];
            ulonglong2 bv1 = *(const ulonglong2*)&W2p[dp * 256 + tx * 8 + 4];
            #pragma unroll
            for (int r = 0; r < 7; r++) {
                uint64_t ap = lds64(&Hst[(row0 + r) * 32 + dp * 2]);
                fma2(acc[r][0], ap, bv0.x);
                fma2(acc[r][1], ap, bv0.y);
                fma2(acc[r][2], ap, bv1.x);
                fma2(acc[r][3], ap, bv1.y);
            }
        }
        __syncthreads();
    }
    {
        const float* bpp = bp2 + tx * 4;
        float b0 = bpp[0], b1 = bpp[1], b2 = bpp[2], b3 = bpp[3];
        const float* wap = wa2 + tx * 4;
        const float* wbp = wb2 + tx * 4;
        float wa0=wap[0], wa1v=wap[1], wa2v=wap[2], wa3=wap[3];
        float wb0=wbp[0], wb1v=wbp[1], wb2v=wbp[2], wb3=wbp[3];
        #pragma unroll
        for (int r = 0; r < 7; r++) {
            int i = row0 + r;
            float v0 = psum(acc[r][0]) + b0, v1 = psum(acc[r][1]) + b1;
            float v2 = psum(acc[r][2]) + b2, v3 = psum(acc[r][3]) + b3;
            int hb = (i >> 1) * 256 + (i & 1);
            h2p[hb + (tx*4+0)*2] = v0;
            h2p[hb + (tx*4+1)*2] = v1;
            h2p[hb + (tx*4+2)*2] = v2;
            h2p[hb + (tx*4+3)*2] = v3;
            atomicAdd(&s2[i], v0*wa0 + v1*wa1v + v2*wa2v + v3*wa3);
            atomicAdd(&t2[i], v0*wb0 + v1*wb1v + v2*wb2v + v3*wb3);
        }
    }
    __syncthreads();

    // attention weights
    float ba = ba2[0];
    const float* adjg = g_adj + (size_t)b * K1P * K1P;
    for (int idx = t; idx < K1P * K1P; idx += 256) {
        int i = idx / K1P, j = idx - i * K1P;
        float e = s2[i] + t2[j] + ba;
        e = e > 0.f ? e : 0.f;
        atts[i * 58 + j] = expf(e) * adjg[idx];
    }
    __syncthreads();
    if (t < K1P) {
        float s = 0.f;
        for (int j = 0; j < K1P; j++) s += atts[t * 58 + j];
        invr[t] = 1.f / s;
    }
    __syncthreads();

    // GEMM2: out2 = att_norm @ h2 + h2, relu
    uint64_t acc2[7][4];
    #pragma unroll
    for (int r = 0; r < 7; r++) { acc2[r][0]=0; acc2[r][1]=0; acc2[r][2]=0; acc2[r][3]=0; }
    #pragma unroll 2
    for (int jp = 0; jp < 28; jp++) {
        ulonglong2 bv0 = *(const ulonglong2*)&h2p[jp * 256 + tx * 8];
        ulonglong2 bv1 = *(const ulonglong2*)&h2p[jp * 256 + tx * 8 + 4];
        #pragma unroll
        for (int r = 0; r < 7; r++) {
            uint64_t ap = lds64(&atts[(row0 + r) * 58 + jp * 2]);
            fma2(acc2[r][0], ap, bv0.x);
            fma2(acc2[r][1], ap, bv0.y);
            fma2(acc2[r][2], ap, bv1.x);
            fma2(acc2[r][3], ap, bv1.y);
        }
    }
    {
        const float* wpp = Wpool2 + tx * 4;
        float w0 = wpp[0], w1 = wpp[1], w2 = wpp[2], w3 = wpp[3];
        #pragma unroll
        for (int r = 0; r < 7; r++) {
            int i = row0 + r;
            float ir = invr[i];
            int hb = (i >> 1) * 256 + (i & 1);
            float4 v;
            v.x = fmaxf(fmaf(psum(acc2[r][0]), ir, h2p[hb + (tx*4+0)*2]), 0.f);
            v.y = fmaxf(fmaf(psum(acc2[r][1]), ir, h2p[hb + (tx*4+1)*2]), 0.f);
            v.z = fmaxf(fmaf(psum(acc2[r][2]), ir, h2p[hb + (tx*4+2)*2]), 0.f);
            v.w = fmaxf(fmaf(psum(acc2[r][3]), ir, h2p[hb + (tx*4+3)*2]), 0.f);
            *(float4*)&h2r[i * 132 + tx * 4] = v;
            atomicAdd(&sc2[i], v.x*w0 + v.y*w1 + v.z*w2 + v.w*w3);
        }
    }
    __syncthreads();

    // top-28 of 56 (pad 64)
    if (t < 64) {
        if (t < K1P) {
            skey[t] = 1.f / (1.f + expf(-(sc2[t] + bpool2[0])));
            sidx[t] = t;
        } else { skey[t] = -1.f; sidx[t] = t; }
    }
    __syncthreads();
    for (int k = 2; k <= 64; k <<= 1) {
        for (int j = k >> 1; j > 0; j >>= 1) {
            if (t < 64) {
                int l = t ^ j;
                if (l > t) {
                    float a = skey[t], c = skey[l];
                    int ia = sidx[t], ib = sidx[l];
                    bool before = (a > c) || (a == c && ia < ib);
                    if (((t & k) == 0) ? !before : before) {
                        skey[t] = c; skey[l] = a;
                        sidx[t] = ib; sidx[l] = ia;
                    }
                }
            }
            __syncthreads();
        }
    }

    if (t < L2D) {
        float s = 0.f;
        #pragma unroll 4
        for (int m = 0; m < K2P; m++)
            s += h2r[sidx[m] * 132 + t] * skey[m];
        mvec[t] = s * (1.f / (float)K2P);
    }
    __syncthreads();
    if (t < L3D) {
        float s = bfc1[t];
        #pragma unroll 8
        for (int d = 0; d < L2D; d++) s = fmaf(mvec[d], Wfc1[t * L2D + d], s);
        y1[t] = fmaxf(s, 0.f);
    }
    __syncthreads();
    if (t == 0) {
        float s = bfc2[0];
        for (int o = 0; o < L3D; o++) s = fmaf(y1[o], Wfc2[o], s);
        out[b] = s;
    }
}

// ---------------- launch ----------------
extern "C" void kernel_launch(void* const* d_in, const int* in_sizes, int n_in,
                              void* d_out, int out_size) {
    const float* x      = (const float*)d_in[0];
    const float* Wp1    = (const float*)d_in[1];
    const float* bp1    = (const float*)d_in[2];
    const float* wa1    = (const float*)d_in[3];
    const float* wb1    = (const float*)d_in[4];
    const float* ba1    = (const float*)d_in[5];
    const float* Wpool1 = (const float*)d_in[6];
    const float* bpool1 = (const float*)d_in[7];
    const float* Wp2    = (const float*)d_in[8];
    const float* bp2    = (const float*)d_in[9];
    const float* wa2    = (const float*)d_in[10];
    const float* wb2    = (const float*)d_in[11];
    const float* ba2    = (const float*)d_in[12];
    const float* Wpool2 = (const float*)d_in[13];
    const float* bpool2 = (const float*)d_in[14];
    const float* Wfc1   = (const float*)d_in[15];
    const float* bfc1   = (const float*)d_in[16];
    const float* Wfc2   = (const float*)d_in[17];
    const float* bfc2   = (const float*)d_in[18];
    float* out = (float*)d_out;

    size_t smem1 = (size_t)G1_FLOATS * sizeof(float);
    size_t smem2 = (size_t)G2_FLOATS * sizeof(float);
    cudaFuncSetAttribute(k_gat1, cudaFuncAttributeMaxDynamicSharedMemorySize, (int)smem1);
    cudaFuncSetAttribute(k_gat2, cudaFuncAttributeMaxDynamicSharedMemorySize, (int)smem2);

    k_preA<<<32, 256>>>(Wp1, bp1, Wp2);
    k_preB<<<1, 256>>>(wa1, wb1, ba1);
    k_gat1<<<BATCH, 256, smem1>>>(x, Wpool1, bpool1);
    k_gat2<<<BATCH, 256, smem2>>>(bp2, wa2, wb2, ba2, Wpool2, bpool2,
                                  Wfc1, bfc1, Wfc2, bfc2, out);
    k_tail<<<1, 32>>>();
}

// round 7
// speedup vs baseline: 1.7192x; 1.4439x over previous
#include <cuda_runtime.h>
#include <math.h>
#include <stdint.h>

#define NODE 112
#define L1D 256
#define L2D 128
#define L3D 64
#define BATCH 2048
#define K1P 56
#define K2P 28

// ---------------- f32x2 packed-FMA helpers (sm_103a FFMA2) ----------------
__device__ __forceinline__ void fma2(uint64_t& d, uint64_t a, uint64_t b) {
    asm("fma.rn.f32x2 %0, %1, %2, %0;" : "+l"(d) : "l"(a), "l"(b));
}
__device__ __forceinline__ float psum(uint64_t v) {
    float2 r; asm("mov.b64 {%0, %1}, %2;" : "=f"(r.x), "=f"(r.y) : "l"(v));
    return r.x + r.y;
}

// ---------------- global scratch ----------------
__device__ float g_H0[NODE * L1D];
__device__ float g_H0P[NODE * L1D];           // k-pair interleaved: [n/2][o][2]
__device__ float g_E1[NODE * NODE];
__device__ float g_Wp2P[L1D * L2D];           // k-pair interleaved: [d/2][o][2]
__device__ float g_h1[(size_t)BATCH * NODE * L1D];
__device__ float g_hp[(size_t)BATCH * K1P * L1D];
__device__ float g_adj[(size_t)BATCH * K1P * K1P];
__device__ float g_dummy;

// ---------------- K-preA ----------------
__global__ void k_preA(const float* __restrict__ Wp1, const float* __restrict__ bp1,
                       const float* __restrict__ Wp2) {
    int t = blockIdx.x * blockDim.x + threadIdx.x;
    int NT = gridDim.x * blockDim.x;
    for (int idx = t; idx < NODE * L1D; idx += NT) {
        int o = idx / NODE, n = idx - o * NODE;
        float v = Wp1[idx] + bp1[o];
        g_H0[n * L1D + o] = v;
        g_H0P[(n >> 1) * (2 * L1D) + o * 2 + (n & 1)] = v;
    }
    for (int idx = t; idx < L1D * L2D; idx += NT) {
        int o = idx >> 8, d = idx & 255;
        g_Wp2P[(d >> 1) * (2 * L2D) + o * 2 + (d & 1)] = Wp2[idx];
    }
}

// ---------------- K-preB ----------------
__global__ void k_preB(const float* __restrict__ wa1, const float* __restrict__ wb1,
                       const float* __restrict__ ba1) {
    __shared__ float s1[NODE], t1[NODE];
    int t = threadIdx.x;
    if (t < NODE) {
        float ss = 0.f, tt = 0.f;
        #pragma unroll 4
        for (int o = 0; o < L1D; o++) {
            float h = g_H0[t * L1D + o];
            ss = fmaf(h, wa1[o], ss);
            tt = fmaf(h, wb1[o], tt);
        }
        s1[t] = ss; t1[t] = tt;
    }
    __syncthreads();
    float ba = ba1[0];
    for (int idx = t; idx < NODE * NODE; idx += blockDim.x) {
        int i = idx / NODE, j = idx - i * NODE;
        float e = s1[i] + t1[j] + ba;
        e = e > 0.f ? e : 0.f;
        g_E1[idx] = expf(e);
    }
}

__global__ void k_tail() { if (threadIdx.x == 0) g_dummy = 1.f; }

// ---------------- K2: GAT1 + pool1 ----------------
// smem: Ws[112*116] | H0p[56*128] | invr[112] | scr[112] | skey[128] | sidx[128] | adjb[56*57]
#define WS_STR   116
#define G1_WS    (NODE * WS_STR)
#define G1_H0P   (G1_WS + 56 * 128)
#define G1_INVR  (G1_H0P + NODE)
#define G1_SCR   (G1_INVR + NODE)
#define G1_SKEY  (G1_SCR + 128)
#define G1_SIDX  (G1_SKEY + 128)
#define G1_ADJB  (G1_SIDX + K1P * 57)
#define G1_FLOATS (G1_ADJB)

__global__ void __launch_bounds__(256, 2)
k_gat1(const float* __restrict__ x, const float* __restrict__ Wpool1,
       const float* __restrict__ bpool1) {
    extern __shared__ float sm[];
    float* Ws   = sm;
    float* H0p  = sm + G1_WS;
    float* invr = sm + G1_H0P;
    float* scr  = sm + G1_INVR;
    float* skey = sm + G1_SCR;
    int*   sidx = (int*)(sm + G1_SKEY);
    float* adjb = sm + G1_SIDX;

    int b = blockIdx.x;
    int t = threadIdx.x;
    const float* xb = x + (size_t)b * NODE * NODE;

    for (int idx = t; idx < NODE * NODE; idx += 256) {
        int i = idx / NODE, j = idx - i * NODE;
        Ws[i * WS_STR + j] = g_E1[idx] * xb[idx];
    }
    if (t < NODE) scr[t] = 0.f;
    __syncthreads();
    if (t < NODE) {
        float s = 0.f;
        #pragma unroll 8
        for (int j = 0; j < NODE; j++) s += Ws[t * WS_STR + j];
        invr[t] = 1.f / s;
    }
    __syncthreads();

    int l = t & 31, w = t >> 5;
    int rh = w >> 2, wc = w & 3;        // row-half, col-stripe
    int rg = l >> 2, cg = l & 3;        // row-group, col-group
    int row0 = rh * 56 + rg * 7;
    int cb = wc * 16 + cg * 4;          // within-tile col (0..63)
    float* h1b = g_h1 + (size_t)b * NODE * L1D;

    for (int ct = 0; ct < 4; ct++) {
        for (int idx = t; idx < 56 * 128; idx += 256) {
            int jp = idx >> 7, rem = idx & 127;
            H0p[idx] = g_H0P[jp * 512 + ct * 128 + rem];
        }
        __syncthreads();
        float wc0, wc1, wc2, wc3;
        {
            const float* wp = Wpool1 + ct * 64 + cb;
            wc0 = wp[0]; wc1 = wp[1]; wc2 = wp[2]; wc3 = wp[3];
        }
        uint64_t acc[7][4];
        #pragma unroll
        for (int r = 0; r < 7; r++) { acc[r][0]=0; acc[r][1]=0; acc[r][2]=0; acc[r][3]=0; }

        #pragma unroll 2
        for (int jp2 = 0; jp2 < 28; jp2++) {
            ulonglong2 av[7];
            #pragma unroll
            for (int r = 0; r < 7; r++)
                av[r] = *(const ulonglong2*)&Ws[(row0 + r) * WS_STR + jp2 * 4];
            {
                const float* bp = &H0p[(jp2 * 2) * 128 + cb * 2];
                ulonglong2 b0 = *(const ulonglong2*)bp;
                ulonglong2 b1 = *(const ulonglong2*)(bp + 4);
                #pragma unroll
                for (int r = 0; r < 7; r++) {
                    fma2(acc[r][0], av[r].x, b0.x);
                    fma2(acc[r][1], av[r].x, b0.y);
                    fma2(acc[r][2], av[r].x, b1.x);
                    fma2(acc[r][3], av[r].x, b1.y);
                }
            }
            {
                const float* bp = &H0p[(jp2 * 2 + 1) * 128 + cb * 2];
                ulonglong2 b0 = *(const ulonglong2*)bp;
                ulonglong2 b1 = *(const ulonglong2*)(bp + 4);
                #pragma unroll
                for (int r = 0; r < 7; r++) {
                    fma2(acc[r][0], av[r].y, b0.x);
                    fma2(acc[r][1], av[r].y, b0.y);
                    fma2(acc[r][2], av[r].y, b1.x);
                    fma2(acc[r][3], av[r].y, b1.y);
                }
            }
        }
        #pragma unroll
        for (int r = 0; r < 7; r++) {
            int i = row0 + r;
            float ir = invr[i];
            int hb = (i >> 1) * 128 + (i & 1);
            float4 v;
            v.x = fmaxf(fmaf(psum(acc[r][0]), ir, H0p[hb + (cb + 0) * 2]), 0.f);
            v.y = fmaxf(fmaf(psum(acc[r][1]), ir, H0p[hb + (cb + 1) * 2]), 0.f);
            v.z = fmaxf(fmaf(psum(acc[r][2]), ir, H0p[hb + (cb + 2) * 2]), 0.f);
            v.w = fmaxf(fmaf(psum(acc[r][3]), ir, H0p[hb + (cb + 3) * 2]), 0.f);
            *(float4*)&h1b[i * L1D + ct * 64 + cb] = v;
            float sp = v.x*wc0 + v.y*wc1 + v.z*wc2 + v.w*wc3;
            sp += __shfl_xor_sync(0xffffffffu, sp, 1);
            sp += __shfl_xor_sync(0xffffffffu, sp, 2);
            if (cg == 0) atomicAdd(&scr[i], sp);
        }
        __syncthreads();
    }

    // sigmoid + bitonic top-56 (pad 128)
    if (t < 128) {
        if (t < NODE) {
            skey[t] = 1.f / (1.f + expf(-(scr[t] + bpool1[0])));
            sidx[t] = t;
        } else { skey[t] = -1.f; sidx[t] = t; }
    }
    __syncthreads();
    for (int k = 2; k <= 128; k <<= 1) {
        for (int j = k >> 1; j > 0; j >>= 1) {
            if (t < 128) {
                int lp = t ^ j;
                if (lp > t) {
                    float a = skey[t], c = skey[lp];
                    int ia = sidx[t], ib = sidx[lp];
                    bool before = (a > c) || (a == c && ia < ib);
                    if (((t & k) == 0) ? !before : before) {
                        skey[t] = c; skey[lp] = a;
                        sidx[t] = ib; sidx[lp] = ia;
                    }
                }
            }
            __syncthreads();
        }
    }

    float* hpb = g_hp + (size_t)b * K1P * L1D;
    for (int idx = t; idx < K1P * L1D; idx += 256) {
        int m = idx >> 8, c = idx & 255;
        hpb[idx] = h1b[sidx[m] * L1D + c] * skey[m];
    }
    for (int idx = t; idx < K1P * K1P; idx += 256) {
        int i = idx / K1P, j = idx - i * K1P;
        adjb[i * 57 + j] = xb[sidx[i] * NODE + sidx[j]];
    }
    __syncthreads();
    if (t < K1P) {
        float s = 0.f;
        for (int j = 0; j < K1P; j++) s += adjb[t * 57 + j];
        invr[t] = 1.f / s;
    }
    __syncthreads();
    float* adjo = g_adj + (size_t)b * K1P * K1P;
    for (int idx = t; idx < K1P * K1P; idx += 256) {
        int i = idx / K1P, j = idx - i * K1P;
        adjo[idx] = adjb[i * 57 + j] * invr[i];
    }
}

// ---------------- K3: GAT2 + pool2 + mean + FC head ----------------
// smem: Hst[56*36] | W2p[16*256] | h2p[28*256] | h2r[56*132] | atts[56*60] | small
#define HST_STR  36
#define ATT_STR  60
#define G2_HST   (56 * HST_STR)
#define G2_W2P   (G2_HST + 16 * 256)
#define G2_H2P   (G2_W2P + 28 * 256)
#define G2_H2R   (G2_H2P + K1P * 132)
#define G2_ATT   (G2_H2R + K1P * ATT_STR)
#define G2_S2    (G2_ATT + 64)
#define G2_T2    (G2_S2 + 64)
#define G2_SC2   (G2_T2 + 64)
#define G2_INVR  (G2_SC2 + 64)
#define G2_SKEY  (G2_INVR + 64)
#define G2_SIDX  (G2_SKEY + 64)
#define G2_MVEC  (G2_SIDX + 128)
#define G2_Y1    (G2_MVEC + 64)
#define G2_FLOATS (G2_Y1)

__global__ void __launch_bounds__(256, 2)
k_gat2(const float* __restrict__ bp2, const float* __restrict__ wa2,
       const float* __restrict__ wb2, const float* __restrict__ ba2,
       const float* __restrict__ Wpool2, const float* __restrict__ bpool2,
       const float* __restrict__ Wfc1, const float* __restrict__ bfc1,
       const float* __restrict__ Wfc2, const float* __restrict__ bfc2,
       float* __restrict__ out) {
    extern __shared__ float sm[];
    float* Hst  = sm;
    float* W2p  = sm + G2_HST;
    float* h2p  = sm + G2_W2P;
    float* h2r  = sm + G2_H2P;
    float* atts = sm + G2_H2R;
    float* s2   = sm + G2_ATT;
    float* t2   = sm + G2_S2;
    float* sc2  = sm + G2_T2;
    float* invr = sm + G2_SC2;
    float* skey = sm + G2_INVR;
    int*   sidx = (int*)(sm + G2_SKEY);
    float* mvec = sm + G2_SIDX;
    float* y1   = sm + G2_MVEC;

    int b = blockIdx.x;
    int t = threadIdx.x;
    const float* hpb = g_hp + (size_t)b * K1P * L1D;

    if (t < K1P) { s2[t] = 0.f; t2[t] = 0.f; sc2[t] = 0.f; }

    int l = t & 31, w = t >> 5;
    int rg = l >> 2, cg = l & 3;
    int row0 = rg * 7;                 // all 56 rows per warp
    int cb = w * 16 + cg * 4;          // cols 0..127

    // GEMM1: h2 = Hs @ Wp2^T + bp2 (56x256 @ 256x128), K tiled by 32
    uint64_t acc[7][4];
    #pragma unroll
    for (int r = 0; r < 7; r++) { acc[r][0]=0; acc[r][1]=0; acc[r][2]=0; acc[r][3]=0; }
    for (int dt = 0; dt < 8; dt++) {
        for (int idx = t; idx < 56 * 32; idx += 256) {
            int i = idx >> 5, dd = idx & 31;
            Hst[i * HST_STR + dd] = hpb[i * L1D + dt * 32 + dd];
        }
        for (int idx = t; idx < 16 * 256; idx += 256)
            W2p[idx] = g_Wp2P[dt * 4096 + idx];
        __syncthreads();
        #pragma unroll
        for (int dp2 = 0; dp2 < 8; dp2++) {
            ulonglong2 av[7];
            #pragma unroll
            for (int r = 0; r < 7; r++)
                av[r] = *(const ulonglong2*)&Hst[(row0 + r) * HST_STR + dp2 * 4];
            {
                const float* bp = &W2p[(dp2 * 2) * 256 + cb * 2];
                ulonglong2 b0 = *(const ulonglong2*)bp;
                ulonglong2 b1 = *(const ulonglong2*)(bp + 4);
                #pragma unroll
                for (int r = 0; r < 7; r++) {
                    fma2(acc[r][0], av[r].x, b0.x);
                    fma2(acc[r][1], av[r].x, b0.y);
                    fma2(acc[r][2], av[r].x, b1.x);
                    fma2(acc[r][3], av[r].x, b1.y);
                }
            }
            {
                const float* bp = &W2p[(dp2 * 2 + 1) * 256 + cb * 2];
                ulonglong2 b0 = *(const ulonglong2*)bp;
                ulonglong2 b1 = *(const ulonglong2*)(bp + 4);
                #pragma unroll
                for (int r = 0; r < 7; r++) {
                    fma2(acc[r][0], av[r].y, b0.x);
                    fma2(acc[r][1], av[r].y, b0.y);
                    fma2(acc[r][2], av[r].y, b1.x);
                    fma2(acc[r][3], av[r].y, b1.y);
                }
            }
        }
        __syncthreads();
    }
    {
        const float* bpp = bp2 + cb;
        float b0 = bpp[0], b1 = bpp[1], b2 = bpp[2], b3 = bpp[3];
        const float* wap = wa2 + cb;
        const float* wbp = wb2 + cb;
        float wa0=wap[0], wa1v=wap[1], wa2v=wap[2], wa3=wap[3];
        float wb0=wbp[0], wb1v=wbp[1], wb2v=wbp[2], wb3=wbp[3];
        #pragma unroll
        for (int r = 0; r < 7; r++) {
            int i = row0 + r;
            float v0 = psum(acc[r][0]) + b0, v1 = psum(acc[r][1]) + b1;
            float v2 = psum(acc[r][2]) + b2, v3 = psum(acc[r][3]) + b3;
            int hb = (i >> 1) * 256 + (i & 1);
            h2p[hb + (cb + 0) * 2] = v0;
            h2p[hb + (cb + 1) * 2] = v1;
            h2p[hb + (cb + 2) * 2] = v2;
            h2p[hb + (cb + 3) * 2] = v3;
            float ssum = v0*wa0 + v1*wa1v + v2*wa2v + v3*wa3;
            float tsum = v0*wb0 + v1*wb1v + v2*wb2v + v3*wb3;
            ssum += __shfl_xor_sync(0xffffffffu, ssum, 1);
            ssum += __shfl_xor_sync(0xffffffffu, ssum, 2);
            tsum += __shfl_xor_sync(0xffffffffu, tsum, 1);
            tsum += __shfl_xor_sync(0xffffffffu, tsum, 2);
            if (cg == 0) {
                atomicAdd(&s2[i], ssum);
                atomicAdd(&t2[i], tsum);
            }
        }
    }
    __syncthreads();

    // attention weights
    float ba = ba2[0];
    const float* adjg = g_adj + (size_t)b * K1P * K1P;
    for (int idx = t; idx < K1P * K1P; idx += 256) {
        int i = idx / K1P, j = idx - i * K1P;
        float e = s2[i] + t2[j] + ba;
        e = e > 0.f ? e : 0.f;
        atts[i * ATT_STR + j] = expf(e) * adjg[idx];
    }
    __syncthreads();
    if (t < K1P) {
        float s = 0.f;
        for (int j = 0; j < K1P; j++) s += atts[t * ATT_STR + j];
        invr[t] = 1.f / s;
    }
    __syncthreads();

    // GEMM2: out2 = att_norm @ h2 + h2, relu
    uint64_t acc2[7][4];
    #pragma unroll
    for (int r = 0; r < 7; r++) { acc2[r][0]=0; acc2[r][1]=0; acc2[r][2]=0; acc2[r][3]=0; }
    #pragma unroll 2
    for (int jp2 = 0; jp2 < 14; jp2++) {
        ulonglong2 av[7];
        #pragma unroll
        for (int r = 0; r < 7; r++)
            av[r] = *(const ulonglong2*)&atts[(row0 + r) * ATT_STR + jp2 * 4];
        {
            const float* bp = &h2p[(jp2 * 2) * 256 + cb * 2];
            ulonglong2 b0 = *(const ulonglong2*)bp;
            ulonglong2 b1 = *(const ulonglong2*)(bp + 4);
            #pragma unroll
            for (int r = 0; r < 7; r++) {
                fma2(acc2[r][0], av[r].x, b0.x);
                fma2(acc2[r][1], av[r].x, b0.y);
                fma2(acc2[r][2], av[r].x, b1.x);
                fma2(acc2[r][3], av[r].x, b1.y);
            }
        }
        {
            const float* bp = &h2p[(jp2 * 2 + 1) * 256 + cb * 2];
            ulonglong2 b0 = *(const ulonglong2*)bp;
            ulonglong2 b1 = *(const ulonglong2*)(bp + 4);
            #pragma unroll
            for (int r = 0; r < 7; r++) {
                fma2(acc2[r][0], av[r].y, b0.x);
                fma2(acc2[r][1], av[r].y, b0.y);
                fma2(acc2[r][2], av[r].y, b1.x);
                fma2(acc2[r][3], av[r].y, b1.y);
            }
        }
    }
    {
        const float* wpp = Wpool2 + cb;
        float w0 = wpp[0], w1 = wpp[1], w2 = wpp[2], w3 = wpp[3];
        #pragma unroll
        for (int r = 0; r < 7; r++) {
            int i = row0 + r;
            float ir = invr[i];
            int hb = (i >> 1) * 256 + (i & 1);
            float4 v;
            v.x = fmaxf(fmaf(psum(acc2[r][0]), ir, h2p[hb + (cb + 0) * 2]), 0.f);
            v.y = fmaxf(fmaf(psum(acc2[r][1]), ir, h2p[hb + (cb + 1) * 2]), 0.f);
            v.z = fmaxf(fmaf(psum(acc2[r][2]), ir, h2p[hb + (cb + 2) * 2]), 0.f);
            v.w = fmaxf(fmaf(psum(acc2[r][3]), ir, h2p[hb + (cb + 3) * 2]), 0.f);
            *(float4*)&h2r[i * 132 + cb] = v;
            float sp = v.x*w0 + v.y*w1 + v.z*w2 + v.w*w3;
            sp += __shfl_xor_sync(0xffffffffu, sp, 1);
            sp += __shfl_xor_sync(0xffffffffu, sp, 2);
            if (cg == 0) atomicAdd(&sc2[i], sp);
        }
    }
    __syncthreads();

    // top-28 of 56 (pad 64)
    if (t < 64) {
        if (t < K1P) {
            skey[t] = 1.f / (1.f + expf(-(sc2[t] + bpool2[0])));
            sidx[t] = t;
        } else { skey[t] = -1.f; sidx[t] = t; }
    }
    __syncthreads();
    for (int k = 2; k <= 64; k <<= 1) {
        for (int j = k >> 1; j > 0; j >>= 1) {
            if (t < 64) {
                int lp = t ^ j;
                if (lp > t) {
                    float a = skey[t], c = skey[lp];
                    int ia = sidx[t], ib = sidx[lp];
                    bool before = (a > c) || (a == c && ia < ib);
                    if (((t & k) == 0) ? !before : before) {
                        skey[t] = c; skey[lp] = a;
                        sidx[t] = ib; sidx[lp] = ia;
                    }
                }
            }
            __syncthreads();
        }
    }

    if (t < L2D) {
        float s = 0.f;
        #pragma unroll 4
        for (int m = 0; m < K2P; m++)
            s += h2r[sidx[m] * 132 + t] * skey[m];
        mvec[t] = s * (1.f / (float)K2P);
    }
    __syncthreads();
    if (t < L3D) {
        float s = bfc1[t];
        #pragma unroll 8
        for (int d = 0; d < L2D; d++) s = fmaf(mvec[d], Wfc1[t * L2D + d], s);
        y1[t] = fmaxf(s, 0.f);
    }
    __syncthreads();
    if (t == 0) {
        float s = bfc2[0];
        for (int o = 0; o < L3D; o++) s = fmaf(y1[o], Wfc2[o], s);
        out[b] = s;
    }
}

// ---------------- launch ----------------
extern "C" void kernel_launch(void* const* d_in, const int* in_sizes, int n_in,
                              void* d_out, int out_size) {
    const float* x      = (const float*)d_in[0];
    const float* Wp1    = (const float*)d_in[1];
    const float* bp1    = (const float*)d_in[2];
    const float* wa1    = (const float*)d_in[3];
    const float* wb1    = (const float*)d_in[4];
    const float* ba1    = (const float*)d_in[5];
    const float* Wpool1 = (const float*)d_in[6];
    const float* bpool1 = (const float*)d_in[7];
    const float* Wp2    = (const float*)d_in[8];
    const float* bp2    = (const float*)d_in[9];
    const float* wa2    = (const float*)d_in[10];
    const float* wb2    = (const float*)d_in[11];
    const float* ba2    = (const float*)d_in[12];
    const float* Wpool2 = (const float*)d_in[13];
    const float* bpool2 = (const float*)d_in[14];
    const float* Wfc1   = (const float*)d_in[15];
    const float* bfc1   = (const float*)d_in[16];
    const float* Wfc2   = (const float*)d_in[17];
    const float* bfc2   = (const float*)d_in[18];
    float* out = (float*)d_out;

    size_t smem1 = (size_t)G1_FLOATS * sizeof(float);
    size_t smem2 = (size_t)G2_FLOATS * sizeof(float);
    cudaFuncSetAttribute(k_gat1, cudaFuncAttributeMaxDynamicSharedMemorySize, (int)smem1);
    cudaFuncSetAttribute(k_gat2, cudaFuncAttributeMaxDynamicSharedMemorySize, (int)smem2);

    k_preA<<<32, 256>>>(Wp1, bp1, Wp2);
    k_preB<<<1, 256>>>(wa1, wb1, ba1);
    k_gat1<<<BATCH, 256, smem1>>>(x, Wpool1, bpool1);
    k_gat2<<<BATCH, 256, smem2>>>(bp2, wa2, wb2, ba2, Wpool2, bpool2,
                                  Wfc1, bfc1, Wfc2, bfc2, out);
    k_tail<<<1, 32>>>();
}

// round 9
// speedup vs baseline: 1.7512x; 1.0186x over previous
#include <cuda_runtime.h>
#include <math.h>
#include <stdint.h>

#define NODE 112
#define L1D 256
#define L2D 128
#define L3D 64
#define BATCH 2048
#define K1P 56
#define K2P 28

// ---------------- f32x2 packed-FMA helpers (sm_103a FFMA2) ----------------
__device__ __forceinline__ void fma2(uint64_t& d, uint64_t a, uint64_t b) {
    asm("fma.rn.f32x2 %0, %1, %2, %0;" : "+l"(d) : "l"(a), "l"(b));
}
__device__ __forceinline__ float psum(uint64_t v) {
    float2 r; asm("mov.b64 {%0, %1}, %2;" : "=f"(r.x), "=f"(r.y) : "l"(v));
    return r.x + r.y;
}

// ---------------- global scratch ----------------
__device__ float g_H0[NODE * L1D];
__device__ float g_H0P[NODE * L1D];           // k-pair interleaved: [n/2][o][2]
__device__ float g_E1[NODE * NODE];
__device__ float g_Wp2T[L1D * L2D];           // plain transposed [d][o]
__device__ float g_h1[(size_t)BATCH * NODE * L1D];
__device__ float g_hp[(size_t)BATCH * K1P * L1D];
__device__ float g_adj[(size_t)BATCH * K1P * K1P];
__device__ float g_dummy;

// ---------------- K-preA ----------------
__global__ void k_preA(const float* __restrict__ Wp1, const float* __restrict__ bp1,
                       const float* __restrict__ Wp2) {
    int t = blockIdx.x * blockDim.x + threadIdx.x;
    int NT = gridDim.x * blockDim.x;
    for (int idx = t; idx < NODE * L1D; idx += NT) {
        int o = idx / NODE, n = idx - o * NODE;
        float v = Wp1[idx] + bp1[o];
        g_H0[n * L1D + o] = v;
        g_H0P[(n >> 1) * (2 * L1D) + o * 2 + (n & 1)] = v;
    }
    for (int idx = t; idx < L1D * L2D; idx += NT) {
        int o = idx >> 8, d = idx & 255;
        g_Wp2T[d * L2D + o] = Wp2[idx];
    }
}

// ---------------- K-preB ----------------
__global__ void k_preB(const float* __restrict__ wa1, const float* __restrict__ wb1,
                       const float* __restrict__ ba1) {
    __shared__ float s1[NODE], t1[NODE];
    int t = threadIdx.x;
    if (t < NODE) {
        float ss = 0.f, tt = 0.f;
        #pragma unroll 4
        for (int o = 0; o < L1D; o++) {
            float h = g_H0[t * L1D + o];
            ss = fmaf(h, wa1[o], ss);
            tt = fmaf(h, wb1[o], tt);
        }
        s1[t] = ss; t1[t] = tt;
    }
    __syncthreads();
    float ba = ba1[0];
    for (int idx = t; idx < NODE * NODE; idx += blockDim.x) {
        int i = idx / NODE, j = idx - i * NODE;
        float e = s1[i] + t1[j] + ba;
        e = e > 0.f ? e : 0.f;
        g_E1[idx] = expf(e);
    }
}

__global__ void k_tail() { if (threadIdx.x == 0) g_dummy = 1.f; }

// ---------------- K2: GAT1 + pool1 (unchanged from R7) ----------------
#define WS_STR   116
#define G1_WS    (NODE * WS_STR)
#define G1_H0P   (G1_WS + 56 * 128)
#define G1_INVR  (G1_H0P + NODE)
#define G1_SCR   (G1_INVR + NODE)
#define G1_SKEY  (G1_SCR + 128)
#define G1_SIDX  (G1_SKEY + 128)
#define G1_ADJB  (G1_SIDX + K1P * 57)
#define G1_FLOATS (G1_ADJB)

__global__ void __launch_bounds__(256, 2)
k_gat1(const float* __restrict__ x, const float* __restrict__ Wpool1,
       const float* __restrict__ bpool1) {
    extern __shared__ float sm[];
    float* Ws   = sm;
    float* H0p  = sm + G1_WS;
    float* invr = sm + G1_H0P;
    float* scr  = sm + G1_INVR;
    float* skey = sm + G1_SCR;
    int*   sidx = (int*)(sm + G1_SKEY);
    float* adjb = sm + G1_SIDX;

    int b = blockIdx.x;
    int t = threadIdx.x;
    const float* xb = x + (size_t)b * NODE * NODE;

    for (int idx = t; idx < NODE * NODE; idx += 256) {
        int i = idx / NODE, j = idx - i * NODE;
        Ws[i * WS_STR + j] = g_E1[idx] * xb[idx];
    }
    if (t < NODE) scr[t] = 0.f;
    __syncthreads();
    if (t < NODE) {
        float s = 0.f;
        #pragma unroll 8
        for (int j = 0; j < NODE; j++) s += Ws[t * WS_STR + j];
        invr[t] = 1.f / s;
    }
    __syncthreads();

    int l = t & 31, w = t >> 5;
    int rh = w >> 2, wc = w & 3;
    int rg = l >> 2, cg = l & 3;
    int row0 = rh * 56 + rg * 7;
    int cb = wc * 16 + cg * 4;
    float* h1b = g_h1 + (size_t)b * NODE * L1D;

    for (int ct = 0; ct < 4; ct++) {
        for (int idx = t; idx < 56 * 128; idx += 256) {
            int jp = idx >> 7, rem = idx & 127;
            H0p[idx] = g_H0P[jp * 512 + ct * 128 + rem];
        }
        __syncthreads();
        float wc0, wc1, wc2, wc3;
        {
            const float* wp = Wpool1 + ct * 64 + cb;
            wc0 = wp[0]; wc1 = wp[1]; wc2 = wp[2]; wc3 = wp[3];
        }
        uint64_t acc[7][4];
        #pragma unroll
        for (int r = 0; r < 7; r++) { acc[r][0]=0; acc[r][1]=0; acc[r][2]=0; acc[r][3]=0; }

        #pragma unroll 2
        for (int jp2 = 0; jp2 < 28; jp2++) {
            ulonglong2 av[7];
            #pragma unroll
            for (int r = 0; r < 7; r++)
                av[r] = *(const ulonglong2*)&Ws[(row0 + r) * WS_STR + jp2 * 4];
            {
                const float* bp = &H0p[(jp2 * 2) * 128 + cb * 2];
                ulonglong2 b0 = *(const ulonglong2*)bp;
                ulonglong2 b1 = *(const ulonglong2*)(bp + 4);
                #pragma unroll
                for (int r = 0; r < 7; r++) {
                    fma2(acc[r][0], av[r].x, b0.x);
                    fma2(acc[r][1], av[r].x, b0.y);
                    fma2(acc[r][2], av[r].x, b1.x);
                    fma2(acc[r][3], av[r].x, b1.y);
                }
            }
            {
                const float* bp = &H0p[(jp2 * 2 + 1) * 128 + cb * 2];
                ulonglong2 b0 = *(const ulonglong2*)bp;
                ulonglong2 b1 = *(const ulonglong2*)(bp + 4);
                #pragma unroll
                for (int r = 0; r < 7; r++) {
                    fma2(acc[r][0], av[r].y, b0.x);
                    fma2(acc[r][1], av[r].y, b0.y);
                    fma2(acc[r][2], av[r].y, b1.x);
                    fma2(acc[r][3], av[r].y, b1.y);
                }
            }
        }
        #pragma unroll
        for (int r = 0; r < 7; r++) {
            int i = row0 + r;
            float ir = invr[i];
            int hb = (i >> 1) * 128 + (i & 1);
            float4 v;
            v.x = fmaxf(fmaf(psum(acc[r][0]), ir, H0p[hb + (cb + 0) * 2]), 0.f);
            v.y = fmaxf(fmaf(psum(acc[r][1]), ir, H0p[hb + (cb + 1) * 2]), 0.f);
            v.z = fmaxf(fmaf(psum(acc[r][2]), ir, H0p[hb + (cb + 2) * 2]), 0.f);
            v.w = fmaxf(fmaf(psum(acc[r][3]), ir, H0p[hb + (cb + 3) * 2]), 0.f);
            *(float4*)&h1b[i * L1D + ct * 64 + cb] = v;
            float sp = v.x*wc0 + v.y*wc1 + v.z*wc2 + v.w*wc3;
            sp += __shfl_xor_sync(0xffffffffu, sp, 1);
            sp += __shfl_xor_sync(0xffffffffu, sp, 2);
            if (cg == 0) atomicAdd(&scr[i], sp);
        }
        __syncthreads();
    }

    if (t < 128) {
        if (t < NODE) {
            skey[t] = 1.f / (1.f + expf(-(scr[t] + bpool1[0])));
            sidx[t] = t;
        } else { skey[t] = -1.f; sidx[t] = t; }
    }
    __syncthreads();
    for (int k = 2; k <= 128; k <<= 1) {
        for (int j = k >> 1; j > 0; j >>= 1) {
            if (t < 128) {
                int lp = t ^ j;
                if (lp > t) {
                    float a = skey[t], c = skey[lp];
                    int ia = sidx[t], ib = sidx[lp];
                    bool before = (a > c) || (a == c && ia < ib);
                    if (((t & k) == 0) ? !before : before) {
                        skey[t] = c; skey[lp] = a;
                        sidx[t] = ib; sidx[lp] = ia;
                    }
                }
            }
            __syncthreads();
        }
    }

    float* hpb = g_hp + (size_t)b * K1P * L1D;
    for (int idx = t; idx < K1P * L1D; idx += 256) {
        int m = idx >> 8, c = idx & 255;
        hpb[idx] = h1b[sidx[m] * L1D + c] * skey[m];
    }
    for (int idx = t; idx < K1P * K1P; idx += 256) {
        int i = idx / K1P, j = idx - i * K1P;
        adjb[i * 57 + j] = xb[sidx[i] * NODE + sidx[j]];
    }
    __syncthreads();
    if (t < K1P) {
        float s = 0.f;
        for (int j = 0; j < K1P; j++) s += adjb[t * 57 + j];
        invr[t] = 1.f / s;
    }
    __syncthreads();
    float* adjo = g_adj + (size_t)b * K1P * K1P;
    for (int idx = t; idx < K1P * K1P; idx += 256) {
        int i = idx / K1P, j = idx - i * K1P;
        adjo[idx] = adjb[i * 57 + j] * invr[i];
    }
}

// ---------------- K3: GAT2 + pool2 + mean + FC head (occ 3) ----------------
// overlay region (6112): [ Hst 56x36 | W2p 32x128 ]  then  [ atts 56x60 ]
// h2p [56][132] (in-place relu'd after GEMM2) | smalls
#define HST_STR  36
#define ATT_STR  60
#define H2P_STR  132
#define G2_OVL   0
#define G2_W2P   (56 * HST_STR)               // 2016
#define G2_H2P   6112
#define G2_S2    (G2_H2P + K1P * H2P_STR)     // 6112+7392=13504
#define G2_T2    (G2_S2 + 64)
#define G2_SC2   (G2_T2 + 64)
#define G2_INVR  (G2_SC2 + 64)
#define G2_SKEY  (G2_INVR + 64)
#define G2_SIDX  (G2_SKEY + 64)
#define G2_MVEC  (G2_SIDX + 64)
#define G2_Y1    (G2_MVEC + 128)
#define G2_FLOATS (G2_Y1 + 64)

__global__ void __launch_bounds__(256, 3)
k_gat2(const float* __restrict__ bp2, const float* __restrict__ wa2,
       const float* __restrict__ wb2, const float* __restrict__ ba2,
       const float* __restrict__ Wpool2, const float* __restrict__ bpool2,
       const float* __restrict__ Wfc1, const float* __restrict__ bfc1,
       const float* __restrict__ Wfc2, const float* __restrict__ bfc2,
       float* __restrict__ out) {
    extern __shared__ float sm[];
    float* Hst  = sm + G2_OVL;                // [56][36]
    float* W2p  = sm + G2_W2P;                // [32][128]
    float* atts = sm + G2_OVL;                // overlays Hst/W2p after GEMM1
    float* h2p  = sm + G2_H2P;                // [56][132]
    float* s2   = sm + G2_S2;
    float* t2   = sm + G2_T2;
    float* sc2  = sm + G2_SC2;
    float* invr = sm + G2_INVR;
    float* skey = sm + G2_SKEY;
    int*   sidx = (int*)(sm + G2_SIDX);
    float* mvec = sm + G2_MVEC;
    float* y1   = sm + G2_Y1;

    int b = blockIdx.x;
    int t = threadIdx.x;
    const float* hpb = g_hp + (size_t)b * K1P * L1D;

    if (t < K1P) { s2[t] = 0.f; t2[t] = 0.f; sc2[t] = 0.f; }

    int l = t & 31, w = t >> 5;
    int rg = l >> 2, cg = l & 3;
    int row0 = rg * 7;                 // rows 0..55
    int cb = w * 16 + cg * 4;          // cols 0..127

    // GEMM1: h2 = Hs @ Wp2^T + bp2 (56x256 @ 256x128), K tiled by 32
    float acc[7][4];
    #pragma unroll
    for (int r = 0; r < 7; r++) { acc[r][0]=0.f; acc[r][1]=0.f; acc[r][2]=0.f; acc[r][3]=0.f; }
    for (int dt = 0; dt < 8; dt++) {
        for (int idx = t; idx < 56 * 32; idx += 256) {
            int i = idx >> 5, dd = idx & 31;
            Hst[i * HST_STR + dd] = hpb[i * L1D + dt * 32 + dd];
        }
        for (int idx = t; idx < 32 * 128; idx += 256)
            W2p[idx] = g_Wp2T[dt * 4096 + idx];
        __syncthreads();
        #pragma unroll
        for (int d4 = 0; d4 < 8; d4++) {
            float4 b0 = *(const float4*)&W2p[(d4 * 4 + 0) * 128 + cb];
            float4 b1 = *(const float4*)&W2p[(d4 * 4 + 1) * 128 + cb];
            float4 b2 = *(const float4*)&W2p[(d4 * 4 + 2) * 128 + cb];
            float4 b3 = *(const float4*)&W2p[(d4 * 4 + 3) * 128 + cb];
            #pragma unroll
            for (int r = 0; r < 7; r++) {
                float4 a = *(const float4*)&Hst[(row0 + r) * HST_STR + d4 * 4];
                acc[r][0] = fmaf(a.x, b0.x, acc[r][0]);
                acc[r][1] = fmaf(a.x, b0.y, acc[r][1]);
                acc[r][2] = fmaf(a.x, b0.z, acc[r][2]);
                acc[r][3] = fmaf(a.x, b0.w, acc[r][3]);
                acc[r][0] = fmaf(a.y, b1.x, acc[r][0]);
                acc[r][1] = fmaf(a.y, b1.y, acc[r][1]);
                acc[r][2] = fmaf(a.y, b1.z, acc[r][2]);
                acc[r][3] = fmaf(a.y, b1.w, acc[r][3]);
                acc[r][0] = fmaf(a.z, b2.x, acc[r][0]);
                acc[r][1] = fmaf(a.z, b2.y, acc[r][1]);
                acc[r][2] = fmaf(a.z, b2.z, acc[r][2]);
                acc[r][3] = fmaf(a.z, b2.w, acc[r][3]);
                acc[r][0] = fmaf(a.w, b3.x, acc[r][0]);
                acc[r][1] = fmaf(a.w, b3.y, acc[r][1]);
                acc[r][2] = fmaf(a.w, b3.z, acc[r][2]);
                acc[r][3] = fmaf(a.w, b3.w, acc[r][3]);
            }
        }
        __syncthreads();
    }
    {
        const float* bpp = bp2 + cb;
        float b0 = bpp[0], b1 = bpp[1], b2 = bpp[2], b3 = bpp[3];
        const float* wap = wa2 + cb;
        const float* wbp = wb2 + cb;
        float wa0=wap[0], wa1v=wap[1], wa2v=wap[2], wa3=wap[3];
        float wb0=wbp[0], wb1v=wbp[1], wb2v=wbp[2], wb3=wbp[3];
        #pragma unroll
        for (int r = 0; r < 7; r++) {
            int i = row0 + r;
            float v0 = acc[r][0] + b0, v1 = acc[r][1] + b1;
            float v2 = acc[r][2] + b2, v3 = acc[r][3] + b3;
            float4 vv = make_float4(v0, v1, v2, v3);
            *(float4*)&h2p[i * H2P_STR + cb] = vv;
            float ssum = v0*wa0 + v1*wa1v + v2*wa2v + v3*wa3;
            float tsum = v0*wb0 + v1*wb1v + v2*wb2v + v3*wb3;
            ssum += __shfl_xor_sync(0xffffffffu, ssum, 1);
            ssum += __shfl_xor_sync(0xffffffffu, ssum, 2);
            tsum += __shfl_xor_sync(0xffffffffu, tsum, 1);
            tsum += __shfl_xor_sync(0xffffffffu, tsum, 2);
            if (cg == 0) {
                atomicAdd(&s2[i], ssum);
                atomicAdd(&t2[i], tsum);
            }
        }
    }
    __syncthreads();

    // attention weights (atts overlays Hst/W2p — both dead now)
    float ba = ba2[0];
    const float* adjg = g_adj + (size_t)b * K1P * K1P;
    for (int idx = t; idx < K1P * K1P; idx += 256) {
        int i = idx / K1P, j = idx - i * K1P;
        float e = s2[i] + t2[j] + ba;
        e = e > 0.f ? e : 0.f;
        atts[i * ATT_STR + j] = expf(e) * adjg[idx];
    }
    __syncthreads();
    if (t < K1P) {
        float s = 0.f;
        for (int j = 0; j < K1P; j++) s += atts[t * ATT_STR + j];
        invr[t] = 1.f / s;
    }
    __syncthreads();

    // GEMM2: out2 = att_norm @ h2 + h2, relu (in-place into h2p)
    float acc2[7][4];
    #pragma unroll
    for (int r = 0; r < 7; r++) { acc2[r][0]=0.f; acc2[r][1]=0.f; acc2[r][2]=0.f; acc2[r][3]=0.f; }
    #pragma unroll 2
    for (int j4 = 0; j4 < 14; j4++) {
        float4 b0 = *(const float4*)&h2p[(j4 * 4 + 0) * H2P_STR + cb];
        float4 b1 = *(const float4*)&h2p[(j4 * 4 + 1) * H2P_STR + cb];
        float4 b2 = *(const float4*)&h2p[(j4 * 4 + 2) * H2P_STR + cb];
        float4 b3 = *(const float4*)&h2p[(j4 * 4 + 3) * H2P_STR + cb];
        #pragma unroll
        for (int r = 0; r < 7; r++) {
            float4 a = *(const float4*)&atts[(row0 + r) * ATT_STR + j4 * 4];
            acc2[r][0] = fmaf(a.x, b0.x, acc2[r][0]);
            acc2[r][1] = fmaf(a.x, b0.y, acc2[r][1]);
            acc2[r][2] = fmaf(a.x, b0.z, acc2[r][2]);
            acc2[r][3] = fmaf(a.x, b0.w, acc2[r][3]);
            acc2[r][0] = fmaf(a.y, b1.x, acc2[r][0]);
            acc2[r][1] = fmaf(a.y, b1.y, acc2[r][1]);
            acc2[r][2] = fmaf(a.y, b1.z, acc2[r][2]);
            acc2[r][3] = fmaf(a.y, b1.w, acc2[r][3]);
            acc2[r][0] = fmaf(a.z, b2.x, acc2[r][0]);
            acc2[r][1] = fmaf(a.z, b2.y, acc2[r][1]);
            acc2[r][2] = fmaf(a.z, b2.z, acc2[r][2]);
            acc2[r][3] = fmaf(a.z, b2.w, acc2[r][3]);
            acc2[r][0] = fmaf(a.w, b3.x, acc2[r][0]);
            acc2[r][1] = fmaf(a.w, b3.y, acc2[r][1]);
            acc2[r][2] = fmaf(a.w, b3.z, acc2[r][2]);
            acc2[r][3] = fmaf(a.w, b3.w, acc2[r][3]);
        }
    }
    __syncthreads();   // all reads of h2p done before in-place update
    {
        const float* wpp = Wpool2 + cb;
        float w0 = wpp[0], w1 = wpp[1], w2 = wpp[2], w3 = wpp[3];
        #pragma unroll
        for (int r = 0; r < 7; r++) {
            int i = row0 + r;
            float ir = invr[i];
            float4 hself = *(const float4*)&h2p[i * H2P_STR + cb];
            float4 v;
            v.x = fmaxf(fmaf(acc2[r][0], ir, hself.x), 0.f);
            v.y = fmaxf(fmaf(acc2[r][1], ir, hself.y), 0.f);
            v.z = fmaxf(fmaf(acc2[r][2], ir, hself.z), 0.f);
            v.w = fmaxf(fmaf(acc2[r][3], ir, hself.w), 0.f);
            *(float4*)&h2p[i * H2P_STR + cb] = v;
            float sp = v.x*w0 + v.y*w1 + v.z*w2 + v.w*w3;
            sp += __shfl_xor_sync(0xffffffffu, sp, 1);
            sp += __shfl_xor_sync(0xffffffffu, sp, 2);
            if (cg == 0) atomicAdd(&sc2[i], sp);
        }
    }
    __syncthreads();

    // top-28 of 56 (pad 64)
    if (t < 64) {
        if (t < K1P) {
            skey[t] = 1.f / (1.f + expf(-(sc2[t] + bpool2[0])));
            sidx[t] = t;
        } else { skey[t] = -1.f; sidx[t] = t; }
    }
    __syncthreads();
    for (int k = 2; k <= 64; k <<= 1) {
        for (int j = k >> 1; j > 0; j >>= 1) {
            if (t < 64) {
                int lp = t ^ j;
                if (lp > t) {
                    float a = skey[t], c = skey[lp];
                    int ia = sidx[t], ib = sidx[lp];
                    bool before = (a > c) || (a == c && ia < ib);
                    if (((t & k) == 0) ? !before : before) {
                        skey[t] = c; skey[lp] = a;
                        sidx[t] = ib; sidx[lp] = ia;
                    }
                }
            }
            __syncthreads();
        }
    }

    if (t < L2D) {
        float s = 0.f;
        #pragma unroll 4
        for (int m = 0; m < K2P; m++)
            s += h2p[sidx[m] * H2P_STR + t] * skey[m];
        mvec[t] = s * (1.f / (float)K2P);
    }
    __syncthreads();
    if (t < L3D) {
        float s = bfc1[t];
        #pragma unroll 8
        for (int d = 0; d < L2D; d++) s = fmaf(mvec[d], Wfc1[t * L2D + d], s);
        y1[t] = fmaxf(s, 0.f);
    }
    __syncthreads();
    if (t == 0) {
        float s = bfc2[0];
        for (int o = 0; o < L3D; o++) s = fmaf(y1[o], Wfc2[o], s);
        out[b] = s;
    }
}

// ---------------- launch ----------------
extern "C" void kernel_launch(void* const* d_in, const int* in_sizes, int n_in,
                              void* d_out, int out_size) {
    const float* x      = (const float*)d_in[0];
    const float* Wp1    = (const float*)d_in[1];
    const float* bp1    = (const float*)d_in[2];
    const float* wa1    = (const float*)d_in[3];
    const float* wb1    = (const float*)d_in[4];
    const float* ba1    = (const float*)d_in[5];
    const float* Wpool1 = (const float*)d_in[6];
    const float* bpool1 = (const float*)d_in[7];
    const float* Wp2    = (const float*)d_in[8];
    const float* bp2    = (const float*)d_in[9];
    const float* wa2    = (const float*)d_in[10];
    const float* wb2    = (const float*)d_in[11];
    const float* ba2    = (const float*)d_in[12];
    const float* Wpool2 = (const float*)d_in[13];
    const float* bpool2 = (const float*)d_in[14];
    const float* Wfc1   = (const float*)d_in[15];
    const float* bfc1   = (const float*)d_in[16];
    const float* Wfc2   = (const float*)d_in[17];
    const float* bfc2   = (const float*)d_in[18];
    float* out = (float*)d_out;

    size_t smem1 = (size_t)G1_FLOATS * sizeof(float);
    size_t smem2 = (size_t)G2_FLOATS * sizeof(float);
    cudaFuncSetAttribute(k_gat1, cudaFuncAttributeMaxDynamicSharedMemorySize, (int)smem1);
    cudaFuncSetAttribute(k_gat2, cudaFuncAttributeMaxDynamicSharedMemorySize, (int)smem2);

    k_preA<<<32, 256>>>(Wp1, bp1, Wp2);
    k_preB<<<1, 256>>>(wa1, wb1, ba1);
    k_gat1<<<BATCH, 256, smem1>>>(x, Wpool1, bpool1);
    k_gat2<<<BATCH, 256, smem2>>>(bp2, wa2, wb2, ba2, Wpool2, bpool2,
                                  Wfc1, bfc1, Wfc2, bfc2, out);
    k_tail<<<1, 32>>>();
}